// round 6
// baseline (speedup 1.0000x reference)
#include <cuda_runtime.h>
#include <cstdint>

#define Bb 4
#define Ss 2048
#define Hh 16
#define BHh 64
#define Dd 64
#define TM 128
#define TN 128
#define NQT 16
#define SCALE_Q 0.1803368801111204f  /* log2(e)/8 */

// tcgen05 exists only on arch-specific sm_10Xa targets.
#if defined(__CUDA_ARCH__) && (defined(__CUDA_ARCH_FEAT_SM103_ALL) || \
    defined(__CUDA_ARCH_FEAT_SM100_ALL) || defined(__CUDA_ARCH_FEAT_SM101_ALL))
#define USE_TC 1
#else
#define USE_TC 0
#endif

// ---------------- SMEM map (tcgen05 path, all tiles 1024-aligned) ----------------
#define SMEM_TMEMPTR 0
#define SMEM_MBAR_S 64
#define SMEM_MBAR_PV 72
#define OFF_QHI 2048
#define OFF_QLO 18432
#define OFF_KHI 34816
#define OFF_KLO 51200
#define OFF_VTH0 67584
#define OFF_VTL0 83968
#define OFF_VTH1 100352
#define OFF_VTL1 116736
#define OFF_PHI 133120
#define OFF_PLO 165888
#define OFF_ONES 198656
#define SMEM_BYTES 202752

// idesc: F32 acc (1<<4), bf16 a (1<<7), bf16 b (1<<10); all K-major, no trans bits
#define IDESC_S ((1u<<4)|(1u<<7)|(1u<<10)|((128/8)<<17)|((128/16)<<24))
#define IDESC_O ((1u<<4)|(1u<<7)|(1u<<10)|((64/8)<<17)|((128/16)<<24))
#define IDESC_L ((1u<<4)|(1u<<7)|(1u<<10)|((16/8)<<17)|((128/16)<<24))

// K-major SW128 descriptor (layout=2, ver=1, SBO=64, LBO=1) — round-3 validated
#define DESC_K  ((uint64_t(2)<<61)|(uint64_t(1)<<46)|(uint64_t(64)<<32)|(uint64_t(1)<<16))
#define MAKE_DESC(a) (DESC_K | ((uint64_t)((a) >> 4) & 0x3FFF))

__device__ float g_linv[BHh * Ss];

__device__ __forceinline__ uint32_t smem_u32(const void* p) {
    uint32_t a;
    asm("{ .reg .u64 t; cvta.to.shared.u64 t, %1; cvt.u32.u64 %0, t; }" : "=r"(a) : "l"(p));
    return a;
}
__device__ __forceinline__ uint32_t sw128(uint32_t x) { return x ^ ((x >> 3) & 0x70); }

#if USE_TC
__device__ __forceinline__ uint32_t elect_one() {
    uint32_t pred;
    asm volatile("{\n\t.reg .pred p;\n\telect.sync _|p, 0xFFFFFFFF;\n\tselp.b32 %0, 1, 0, p;\n\t}"
                 : "=r"(pred));
    return pred;
}
__device__ __forceinline__ float fexp2(float x) {
    float r;
    asm("ex2.approx.f32 %0, %1;" : "=f"(r) : "f"(x));
    return r;
}
__device__ __forceinline__ uint32_t pack_bf16(float lo, float hi) {
    uint32_t r;
    asm("cvt.rn.bf16x2.f32 %0, %1, %2;" : "=r"(r) : "f"(hi), "f"(lo));
    return r;
}
__device__ __forceinline__ float lofl(uint32_t u) { return __uint_as_float(u << 16); }
__device__ __forceinline__ float hifl(uint32_t u) { return __uint_as_float(u & 0xffff0000u); }

#define MBAR_INIT(addr, cnt) \
    asm volatile("mbarrier.init.shared.b64 [%0], %1;" :: "r"(addr), "r"(cnt) : "memory")
#define MBAR_INVAL(addr) \
    asm volatile("mbarrier.inval.shared.b64 [%0];" :: "r"(addr) : "memory")
#define MBAR_WAIT(addr, parity) do { \
    uint32_t _m = (uint32_t)(addr); uint32_t _p = (uint32_t)(parity); uint32_t _d; \
    asm volatile("{\n\t.reg .pred p;\n\t" \
        "mbarrier.try_wait.parity.acquire.cta.shared::cta.b64 p, [%1], %2;\n\t" \
        "selp.b32 %0, 1, 0, p;\n\t}" : "=r"(_d) : "r"(_m), "r"(_p) : "memory"); \
    if (!_d) { \
        asm volatile("{\n\t.reg .pred P1;\n\t" \
            "WL_%=:\n\t" \
            "mbarrier.try_wait.parity.acquire.cta.shared::cta.b64 P1, [%0], %1, 0x989680;\n\t" \
            "@P1 bra.uni WD_%=;\n\t" \
            "bra.uni WL_%=;\n\t" \
            "WD_%=:\n\t}" :: "r"(_m), "r"(_p) : "memory"); \
    } \
} while (0)

#define TC_ALLOC(smem_addr, ncols) \
    asm volatile("tcgen05.alloc.cta_group::1.sync.aligned.shared::cta.b32 [%0], %1;" \
                 :: "r"((uint32_t)(smem_addr)), "r"((uint32_t)(ncols)) : "memory")
#define TC_DEALLOC(tmem, ncols) \
    asm volatile("tcgen05.dealloc.cta_group::1.sync.aligned.b32 %0, %1;" \
                 :: "r"(tmem), "r"((uint32_t)(ncols)))
#define TC_RELINQ() \
    asm volatile("tcgen05.relinquish_alloc_permit.cta_group::1.sync.aligned;")
#define TC_COMMIT(mbar) \
    asm volatile("tcgen05.commit.cta_group::1.mbarrier::arrive::one.shared::cluster.b64 [%0];" \
                 :: "r"((uint32_t)(mbar)) : "memory")
#define TC_FENCE_AFTER()  asm volatile("tcgen05.fence::after_thread_sync;" ::: "memory")
#define TC_WAIT_LD() asm volatile("tcgen05.wait::ld.sync.aligned;" ::: "memory")
#define FENCE_ASYNC_SHARED() asm volatile("fence.proxy.async.shared::cta;" ::: "memory")

#define TC_LD_X32(r, addr) \
    asm volatile("tcgen05.ld.sync.aligned.32x32b.x32.b32 " \
        "{%0, %1, %2, %3, %4, %5, %6, %7, " \
        " %8, %9, %10, %11, %12, %13, %14, %15, " \
        " %16, %17, %18, %19, %20, %21, %22, %23, " \
        " %24, %25, %26, %27, %28, %29, %30, %31}, [%32];" \
        : "=r"((r)[0]),  "=r"((r)[1]),  "=r"((r)[2]),  "=r"((r)[3]), \
          "=r"((r)[4]),  "=r"((r)[5]),  "=r"((r)[6]),  "=r"((r)[7]), \
          "=r"((r)[8]),  "=r"((r)[9]),  "=r"((r)[10]), "=r"((r)[11]), \
          "=r"((r)[12]), "=r"((r)[13]), "=r"((r)[14]), "=r"((r)[15]), \
          "=r"((r)[16]), "=r"((r)[17]), "=r"((r)[18]), "=r"((r)[19]), \
          "=r"((r)[20]), "=r"((r)[21]), "=r"((r)[22]), "=r"((r)[23]), \
          "=r"((r)[24]), "=r"((r)[25]), "=r"((r)[26]), "=r"((r)[27]), \
          "=r"((r)[28]), "=r"((r)[29]), "=r"((r)[30]), "=r"((r)[31]) \
        : "r"(addr))
#define TC_LD_X1(r0, addr) \
    asm volatile("tcgen05.ld.sync.aligned.32x32b.x1.b32 {%0}, [%1];" : "=r"(r0) : "r"(addr))

__device__ __forceinline__ void mma_bf16(uint32_t d, uint64_t a, uint64_t b,
                                         uint32_t idesc, uint32_t acc) {
    asm volatile("{\n\t.reg .pred p;\n\tsetp.ne.u32 p, %5, 0;\n\t"
                 "tcgen05.mma.cta_group::1.kind::f16 [%0], %1, %2, %3, {%4, %4, %4, %4}, p;\n\t}"
                 :: "r"(d), "l"(a), "l"(b), "r"(idesc), "r"(0u), "r"(acc) : "memory");
}

// split 8 scaled floats into one 16B bf16-hi chunk + one 16B bf16-lo chunk
__device__ __forceinline__ void split8(const float* x, uint4& H, uint4& L) {
    H.x = pack_bf16(x[0], x[1]); H.y = pack_bf16(x[2], x[3]);
    H.z = pack_bf16(x[4], x[5]); H.w = pack_bf16(x[6], x[7]);
    L.x = pack_bf16(x[0] - lofl(H.x), x[1] - hifl(H.x));
    L.y = pack_bf16(x[2] - lofl(H.y), x[3] - hifl(H.y));
    L.z = pack_bf16(x[4] - lofl(H.z), x[5] - hifl(H.z));
    L.w = pack_bf16(x[6] - lofl(H.w), x[7] - hifl(H.w));
}

// read a 128x64 fp32 tile (row stride Hh*Dd) into 8 float4 regs
__device__ __forceinline__ void ldg_tile(const float* __restrict__ src, float4* f, int t) {
    const float* p = src + (size_t)(t >> 1) * (Hh * Dd) + (t & 1) * 32;
#pragma unroll
    for (int j = 0; j < 8; j++) f[j] = *(const float4*)(p + 4 * j);
}

// bf16-split tile, store swizzled K-major (128 rows x 64 bf16 = one SW128 atom column)
__device__ __forceinline__ void sts_tile(const float4* f, uint32_t sbp,
                                         uint32_t off_hi, uint32_t off_lo,
                                         float scale, int t) {
    const int r = t >> 1, c0 = (t & 1) * 32;
    const uint32_t rowbase = ((uint32_t)(r >> 3) << 10) + ((uint32_t)(r & 7) << 7);
#pragma unroll
    for (int c = 0; c < 4; c++) {
        float x[8];
        const float4 a = f[2 * c], b = f[2 * c + 1];
        x[0] = a.x * scale; x[1] = a.y * scale; x[2] = a.z * scale; x[3] = a.w * scale;
        x[4] = b.x * scale; x[5] = b.y * scale; x[6] = b.z * scale; x[7] = b.w * scale;
        uint4 H, L;
        split8(x, H, L);
        uint32_t ad = sw128(rowbase + (uint32_t)(c0 + 8 * c) * 2);
        asm volatile("st.shared.v4.b32 [%0], {%1,%2,%3,%4};"
                     :: "r"(sbp + off_hi + ad), "r"(H.x), "r"(H.y), "r"(H.z), "r"(H.w));
        asm volatile("st.shared.v4.b32 [%0], {%1,%2,%3,%4};"
                     :: "r"(sbp + off_lo + ad), "r"(L.x), "r"(L.y), "r"(L.z), "r"(L.w));
    }
}

// bf16-split V and store TRANSPOSED as V^T [64 d rows x 128 token cols] K-major
// (round-3-validated geometry: 2 atom columns of 64 tokens, 8 atom rows)
__device__ __forceinline__ void sts_vt(const float4* f, uint32_t sbp,
                                       uint32_t off_hi, uint32_t off_lo, int t) {
    const int tok = t >> 1, c0 = (t & 1) * 32;
    const uint32_t tokpart = ((uint32_t)(tok >> 6) << 13) + ((uint32_t)(tok & 63) << 1);
    const float* x = (const float*)f;
#pragma unroll
    for (int j = 0; j < 32; j++) {
        const int d = c0 + j;
        float val = x[j];
        uint16_t hb;
        asm("cvt.rn.bf16.f32 %0, %1;" : "=h"(hb) : "f"(val));
        float hf = __uint_as_float((uint32_t)hb << 16);
        uint16_t lb;
        asm("cvt.rn.bf16.f32 %0, %1;" : "=h"(lb) : "f"(val - hf));
        uint32_t ad = sw128(((uint32_t)(d >> 3) << 10) + ((uint32_t)(d & 7) << 7) + tokpart);
        asm volatile("st.shared.b16 [%0], %1;" :: "r"(sbp + off_hi + ad), "h"(hb));
        asm volatile("st.shared.b16 [%0], %1;" :: "r"(sbp + off_lo + ad), "h"(lb));
    }
}
#endif  // USE_TC

__global__ __launch_bounds__(256, 1) __cluster_dims__(1, 1, 1)
void attn_pass1_tc(const float* __restrict__ q, const float* __restrict__ k,
                   const float* __restrict__ v, float* __restrict__ out,
                   float* __restrict__ attn) {
    extern __shared__ char sm[];
    const int t = threadIdx.x;
    const int w = t >> 5, lid = t & 31;
    const int bh = blockIdx.y, b = bh >> 4, h = bh & 15;
    const int qt = (NQT - 1) - blockIdx.x;  // big tiles first
    const int qr0 = qt * TM;

    const float* qb = q + (size_t)b * Ss * Hh * Dd + (size_t)h * Dd;
    const float* kb = k + (size_t)b * Ss * Hh * Dd + (size_t)h * Dd;
    const float* vb = v + (size_t)b * Ss * Hh * Dd + (size_t)h * Dd;
    float* attnb = attn + (size_t)bh * Ss * Ss;

#if USE_TC
    // ====== tcgen05 path: S^T = K·Q^T (lanes=k tokens), O = P·V^T, L = P·1 ======
    const uint32_t sb = smem_u32(sm);

    if (w == 0) TC_ALLOC(sb + SMEM_TMEMPTR, 256);
    if (t == 0) {
        MBAR_INIT(sb + SMEM_MBAR_S, 1);
        MBAR_INIT(sb + SMEM_MBAR_PV, 1);
    }
    // ones tile (all bf16 1.0) + prologue loads: Q(scaled), K(0), V^T(0)->buf0
    for (int i = t; i < 1024; i += 256)
        ((uint32_t*)(sm + OFF_ONES))[i] = 0x3F803F80u;
    {
        float4 f[8];
        ldg_tile(qb + (size_t)qr0 * (Hh * Dd), f, t);
        sts_tile(f, sb, OFF_QHI, OFF_QLO, SCALE_Q, t);
        ldg_tile(kb, f, t);
        sts_tile(f, sb, OFF_KHI, OFF_KLO, 1.0f, t);
        ldg_tile(vb, f, t);
        sts_vt(f, sb, OFF_VTH0, OFF_VTL0, t);
    }
    FENCE_ASYNC_SHARED();
    __syncthreads();

    uint32_t tmem;
    asm volatile("ld.shared.b32 %0, [%1];" : "=r"(tmem) : "r"(sb + SMEM_TMEMPTR));
    const uint32_t ST_T = tmem;        // S^T: fp32 cols 0..127, lanes = k tokens
    const uint32_t O_T  = tmem + 128;  // O: 64 cols, lanes = q rows
    const uint32_t L_T  = tmem + 192;  // row sums: 16 cols, lanes = q rows

    const uint64_t dq_hi = MAKE_DESC(sb + OFF_QHI);
    const uint64_t dq_lo = MAKE_DESC(sb + OFF_QLO);
    const uint64_t dk_hi = MAKE_DESC(sb + OFF_KHI);
    const uint64_t dk_lo = MAKE_DESC(sb + OFF_KLO);
    const uint64_t dvh[2] = {MAKE_DESC(sb + OFF_VTH0), MAKE_DESC(sb + OFF_VTH1)};
    const uint64_t dvl[2] = {MAKE_DESC(sb + OFF_VTL0), MAKE_DESC(sb + OFF_VTL1)};
    const uint64_t dp_hi = MAKE_DESC(sb + OFF_PHI);
    const uint64_t dp_lo = MAKE_DESC(sb + OFF_PLO);
    const uint64_t dones = MAKE_DESC(sb + OFF_ONES);

    // first S^T MMA (K-dim = d: 4 chunks x 3 split terms)
    if (w == 0 && elect_one()) {
#pragma unroll
        for (int kc = 0; kc < 4; kc++) {
            uint64_t o = (uint64_t)(kc << 1);
            mma_bf16(ST_T, dk_hi + o, dq_hi + o, IDESC_S, kc > 0);
            mma_bf16(ST_T, dk_hi + o, dq_lo + o, IDESC_S, 1);
            mma_bf16(ST_T, dk_lo + o, dq_hi + o, IDESC_S, 1);
        }
        TC_COMMIT(sb + SMEM_MBAR_S);
    }

    const int sp = w & 3;
    const int ch = (w >> 2) * 64;          // q-column half handled by this warp
    const int mk = sp * 32 + lid;          // TMEM lane (k token; later q row)
    const uint32_t colpart = ((uint32_t)(mk >> 6) << 14) + ((uint32_t)(mk & 63) << 1);
    int s_ph = 0, pv_ph = 0;

    for (int kt = 0; kt <= qt; kt++) {
        const int kc0 = kt * TN;
        const bool diag = (kt == qt);
        float4 fk[8], fv[8];

        MBAR_WAIT(sb + SMEM_MBAR_S, s_ph);
        s_ph ^= 1;
        TC_FENCE_AFTER();

        if (kt < qt) ldg_tile(kb + (size_t)(kc0 + TN) * (Hh * Dd), fk, t);

#pragma unroll
        for (int half = 0; half < 2; half++) {
            uint32_t r[32];
            TC_LD_X32(r, ST_T + ch + half * 32);
            TC_WAIT_LD();
            const int cl0 = ch + half * 32;
            float* arow = attnb + (size_t)(qr0 + cl0) * Ss + kc0 + mk;
            float e[32];
#pragma unroll
            for (int j = 0; j < 32; j++) {
                const int ql = cl0 + j;
                float ev = fexp2(__uint_as_float(r[j]));
                if (diag && (mk > ql)) ev = 0.f;
                e[j] = ev;
                arow[(size_t)j * Ss] = ev;      // coalesced: lanes = consecutive k
            }
            if (half == 0) {
                if (kt < qt) ldg_tile(vb + (size_t)(kc0 + TN) * (Hh * Dd), fv, t);
                // PV(kt-1) must be done before P is overwritten (explicit, validated ordering)
                if (kt > 0) { MBAR_WAIT(sb + SMEM_MBAR_PV, pv_ph); pv_ph ^= 1; }
            }
#pragma unroll
            for (int j = 0; j < 32; j++) {
                const int ql = cl0 + j;
                uint16_t hb;
                asm("cvt.rn.bf16.f32 %0, %1;" : "=h"(hb) : "f"(e[j]));
                float hf = __uint_as_float((uint32_t)hb << 16);
                uint16_t lb;
                asm("cvt.rn.bf16.f32 %0, %1;" : "=h"(lb) : "f"(e[j] - hf));
                uint32_t ad = sw128(((uint32_t)(ql >> 3) << 10) +
                                    ((uint32_t)(ql & 7) << 7) + colpart);
                asm volatile("st.shared.b16 [%0], %1;" :: "r"(sb + OFF_PHI + ad), "h"(hb));
                asm volatile("st.shared.b16 [%0], %1;" :: "r"(sb + OFF_PLO + ad), "h"(lb));
            }
        }
        FENCE_ASYNC_SHARED();
        __syncthreads();

        // O += P·V^T (round-3-validated 64-row B offsets) and L += P·1; commit per iter
        if (w == 0 && elect_one()) {
            const int vbuf = kt & 1;
#pragma unroll
            for (int kc = 0; kc < 8; kc++) {
                uint64_t oa = (uint64_t)(((kc >> 2) << 10) + ((kc & 3) << 1));
                uint64_t ob = (uint64_t)(((kc >> 2) << 9) + ((kc & 3) << 1));
                mma_bf16(O_T, dp_hi + oa, dvh[vbuf] + ob, IDESC_O, !(kt == 0 && kc == 0));
                mma_bf16(O_T, dp_hi + oa, dvl[vbuf] + ob, IDESC_O, 1);
                mma_bf16(O_T, dp_lo + oa, dvh[vbuf] + ob, IDESC_O, 1);
            }
#pragma unroll
            for (int kc = 0; kc < 8; kc++) {
                uint64_t oa = (uint64_t)(((kc >> 2) << 10) + ((kc & 3) << 1));
                uint64_t oo = (uint64_t)(((kc >> 2) << 7) + ((kc & 3) << 1));
                mma_bf16(L_T, dp_hi + oa, dones + oo, IDESC_L, !(kt == 0 && kc == 0));
                mma_bf16(L_T, dp_lo + oa, dones + oo, IDESC_L, 1);
            }
            TC_COMMIT(sb + SMEM_MBAR_PV);
        }

        if (kt < qt) {
            sts_tile(fk, sb, OFF_KHI, OFF_KLO, 1.0f, t);
            const uint32_t vh = ((kt + 1) & 1) ? OFF_VTH1 : OFF_VTH0;
            const uint32_t vl = ((kt + 1) & 1) ? OFF_VTL1 : OFF_VTL0;
            sts_vt(fv, sb, vh, vl, t);
            FENCE_ASYNC_SHARED();
            __syncthreads();
            if (w == 0 && elect_one()) {
#pragma unroll
                for (int kc = 0; kc < 4; kc++) {
                    uint64_t o = (uint64_t)(kc << 1);
                    mma_bf16(ST_T, dk_hi + o, dq_hi + o, IDESC_S, kc > 0);
                    mma_bf16(ST_T, dk_hi + o, dq_lo + o, IDESC_S, 1);
                    mma_bf16(ST_T, dk_lo + o, dq_hi + o, IDESC_S, 1);
                }
                TC_COMMIT(sb + SMEM_MBAR_S);
            }
        }
    }

    // zero-fill masked (strictly upper) region of attn
    {
        const int zc0 = (qt + 1) * TN;
        const float4 z = make_float4(0.f, 0.f, 0.f, 0.f);
        for (int rr = w; rr < TM; rr += 8) {
            float* rowp = attnb + (size_t)(qr0 + rr) * Ss;
            for (int c = zc0 + lid * 4; c < Ss; c += 128)
                *(float4*)(rowp + c) = z;
        }
    }

    // final: wait last PV, read L and O (lanes = q rows), normalize, store
    MBAR_WAIT(sb + SMEM_MBAR_PV, pv_ph);
    TC_FENCE_AFTER();
    {
        uint32_t lr;
        TC_LD_X1(lr, L_T);
        uint32_t r[32];
        TC_LD_X32(r, O_T + (w >> 2) * 32);
        TC_WAIT_LD();
        const float inv = 1.0f / __uint_as_float(lr);
        if (w < 4) g_linv[bh * Ss + qr0 + mk] = inv;
        float* op = out + (size_t)b * Ss * Hh * Dd + (size_t)(qr0 + mk) * (Hh * Dd) +
                    h * Dd + (w >> 2) * 32;
#pragma unroll
        for (int j = 0; j < 32; j += 4) {
            float4 o4 = make_float4(__uint_as_float(r[j]) * inv,
                                    __uint_as_float(r[j + 1]) * inv,
                                    __uint_as_float(r[j + 2]) * inv,
                                    __uint_as_float(r[j + 3]) * inv);
            *(float4*)(op + j) = o4;
        }
    }
    __syncthreads();
    if (t == 0) { MBAR_INVAL(sb + SMEM_MBAR_S); MBAR_INVAL(sb + SMEM_MBAR_PV); }
    __syncthreads();
    if (w == 0) {
        TC_RELINQ();
        TC_DEALLOC(tmem, 256);
    }
#else
    // =========================== FFMA fallback (plain sm_103 pass) ===========================
    float* q_t = (float*)sm;
    float* k_t = (float*)(sm + 33792);
    float* v_s = (float*)(sm + 67584);
    float* p_s = (float*)(sm + 102400);
    const int ty = t >> 4, tx = t & 15;
    {
#pragma unroll
        for (int rr = 0; rr < 2; rr++) {
            int row = rr * 64 + (t >> 2);
            int c0 = (t & 3) * 16;
            const float* src = qb + (size_t)(qr0 + row) * (Hh * Dd) + c0;
#pragma unroll
            for (int c4 = 0; c4 < 4; c4++) {
                float4 val = *(const float4*)(src + c4 * 4);
                int d = c0 + c4 * 4;
                q_t[(d + 0) * 132 + row] = val.x * 0.125f;
                q_t[(d + 1) * 132 + row] = val.y * 0.125f;
                q_t[(d + 2) * 132 + row] = val.z * 0.125f;
                q_t[(d + 3) * 132 + row] = val.w * 0.125f;
            }
        }
    }
    __syncthreads();
    float acc_o[8][4];
#pragma unroll
    for (int i = 0; i < 8; i++)
#pragma unroll
        for (int j = 0; j < 4; j++) acc_o[i][j] = 0.f;
    float lsum[8] = {0.f, 0.f, 0.f, 0.f, 0.f, 0.f, 0.f, 0.f};
    for (int kt = 0; kt <= qt; kt++) {
        const int kc0 = kt * TN;
#pragma unroll
        for (int rr = 0; rr < 2; rr++) {
            int row = rr * 64 + (t >> 2);
            int c0 = (t & 3) * 16;
            const float* src = kb + (size_t)(kc0 + row) * (Hh * Dd) + c0;
#pragma unroll
            for (int c4 = 0; c4 < 4; c4++) {
                float4 val = *(const float4*)(src + c4 * 4);
                int d = c0 + c4 * 4;
                k_t[(d + 0) * 132 + row] = val.x;
                k_t[(d + 1) * 132 + row] = val.y;
                k_t[(d + 2) * 132 + row] = val.z;
                k_t[(d + 3) * 132 + row] = val.w;
            }
        }
        {
            int row = t >> 1;
            int c0 = (t & 1) * 32;
            const float* src = vb + (size_t)(kc0 + row) * (Hh * Dd) + c0;
#pragma unroll
            for (int c4 = 0; c4 < 8; c4++)
                *(float4*)&v_s[row * 68 + c0 + c4 * 4] = *(const float4*)(src + c4 * 4);
        }
        __syncthreads();
        float s_[8][8];
#pragma unroll
        for (int i = 0; i < 8; i++)
#pragma unroll
            for (int j = 0; j < 8; j++) s_[i][j] = 0.f;
#pragma unroll 2
        for (int d = 0; d < 64; d++) {
            float a[8], bv[8];
            *(float4*)&a[0] = *(const float4*)&q_t[d * 132 + 8 * ty];
            *(float4*)&a[4] = *(const float4*)&q_t[d * 132 + 8 * ty + 4];
            *(float4*)&bv[0] = *(const float4*)&k_t[d * 132 + 8 * tx];
            *(float4*)&bv[4] = *(const float4*)&k_t[d * 132 + 8 * tx + 4];
#pragma unroll
            for (int i = 0; i < 8; i++)
#pragma unroll
                for (int j = 0; j < 8; j++) s_[i][j] += a[i] * bv[j];
        }
#pragma unroll
        for (int i = 0; i < 8; i++) {
            const int rg = qr0 + 8 * ty + i;
            float p[8];
#pragma unroll
            for (int j = 0; j < 8; j++) {
                const int cg = kc0 + 8 * tx + j;
                float e = (cg <= rg) ? __expf(s_[i][j]) : 0.f;
                p[j] = e;
                lsum[i] += e;
            }
            *(float4*)&p_s[(8 * ty + i) * 132 + 8 * tx] = *(float4*)&p[0];
            *(float4*)&p_s[(8 * ty + i) * 132 + 8 * tx + 4] = *(float4*)&p[4];
            float* gp = &attnb[(size_t)rg * Ss + kc0 + 8 * tx];
            *(float4*)gp = *(float4*)&p[0];
            *(float4*)(gp + 4) = *(float4*)&p[4];
        }
        __syncthreads();
#pragma unroll 2
        for (int n = 0; n < 128; n++) {
            float4 vv = *(const float4*)&v_s[n * 68 + 4 * tx];
#pragma unroll
            for (int i = 0; i < 8; i++) {
                float pv = p_s[(8 * ty + i) * 132 + n];
                acc_o[i][0] += pv * vv.x;
                acc_o[i][1] += pv * vv.y;
                acc_o[i][2] += pv * vv.z;
                acc_o[i][3] += pv * vv.w;
            }
        }
        __syncthreads();
    }
    {
        const int zc0 = (qt + 1) * TN;
        const float4 z = make_float4(0.f, 0.f, 0.f, 0.f);
        for (int rr = w; rr < TM; rr += 8) {
            float* rowp = attnb + (size_t)(qr0 + rr) * Ss;
            for (int c = zc0 + lid * 4; c < Ss; c += 128)
                *(float4*)(rowp + c) = z;
        }
    }
    float inv[8];
#pragma unroll
    for (int i = 0; i < 8; i++) {
        float s = lsum[i];
        s += __shfl_xor_sync(0xffffffffu, s, 1);
        s += __shfl_xor_sync(0xffffffffu, s, 2);
        s += __shfl_xor_sync(0xffffffffu, s, 4);
        s += __shfl_xor_sync(0xffffffffu, s, 8);
        inv[i] = 1.0f / s;
    }
    if (tx == 0) {
#pragma unroll
        for (int i = 0; i < 8; i++)
            g_linv[bh * Ss + qr0 + 8 * ty + i] = inv[i];
    }
#pragma unroll
    for (int i = 0; i < 8; i++) {
        const int rg = qr0 + 8 * ty + i;
        float4 o4 = make_float4(acc_o[i][0] * inv[i], acc_o[i][1] * inv[i],
                                acc_o[i][2] * inv[i], acc_o[i][3] * inv[i]);
        *(float4*)&out[(size_t)b * Ss * Hh * Dd + (size_t)rg * (Hh * Dd) + h * Dd + 4 * tx] = o4;
    }
#endif
}

// Normalize the causal prefix. Pair row j with row 2047-j for load balance.
__global__ __launch_bounds__(256) void attn_norm2(float* __restrict__ attn) {
    const int x = blockIdx.x;
    const int bh = x >> 10;
    const int jl = x & 1023;
    float* base = attn + (size_t)bh * Ss * Ss;
#pragma unroll
    for (int which = 0; which < 2; which++) {
        const int row = which ? (Ss - 1 - jl) : jl;
        const float inv = g_linv[bh * Ss + row];
        const int n4 = (row + 4) >> 2;
        float4* p = (float4*)(base + (size_t)row * Ss);
        for (int c = threadIdx.x; c < n4; c += 256) {
            float4 u = p[c];
            u.x *= inv; u.y *= inv; u.z *= inv; u.w *= inv;
            p[c] = u;
        }
    }
}

extern "C" void kernel_launch(void* const* d_in, const int* in_sizes, int n_in,
                              void* d_out, int out_size) {
    const float* q = (const float*)d_in[0];
    const float* k = (const float*)d_in[1];
    const float* v = (const float*)d_in[2];
    // d_in[3] = causal mask (deterministic triu) -> handled analytically

    float* out = (float*)d_out;
    float* attn = (float*)d_out + (size_t)Bb * Ss * Hh * Dd;

    cudaFuncSetAttribute(attn_pass1_tc, cudaFuncAttributeMaxDynamicSharedMemorySize,
                         SMEM_BYTES);

    dim3 grid(NQT, BHh);
    attn_pass1_tc<<<grid, 256, SMEM_BYTES>>>(q, k, v, out, attn);
    attn_norm2<<<BHh * 1024, 256>>>(attn);
}

// round 7
// speedup vs baseline: 1.0549x; 1.0549x over previous
#include <cuda_runtime.h>
#include <cstdint>

#define Bb 4
#define Ss 2048
#define Hh 16
#define BHh 64
#define Dd 64
#define TM 128
#define TN 128
#define NQT 16
#define NTHR 512
#define SCALE_Q 0.1803368801111204f  /* log2(e)/8 */

// tcgen05 exists only on arch-specific sm_10Xa targets.
#if defined(__CUDA_ARCH__) && (defined(__CUDA_ARCH_FEAT_SM103_ALL) || \
    defined(__CUDA_ARCH_FEAT_SM100_ALL) || defined(__CUDA_ARCH_FEAT_SM101_ALL))
#define USE_TC 1
#else
#define USE_TC 0
#endif

// ---------------- SMEM map (tcgen05 path, all tiles 1024-aligned) ----------------
#define SMEM_TMEMPTR 0
#define SMEM_MBAR_S 64
#define SMEM_MBAR_PV 72
#define OFF_QHI 2048
#define OFF_QLO 18432
#define OFF_KHI 34816
#define OFF_KLO 51200
#define OFF_VTH0 67584
#define OFF_VTL0 83968
#define OFF_VTH1 100352
#define OFF_VTL1 116736
#define OFF_PHI 133120
#define OFF_PLO 165888
#define OFF_ONES 198656
#define SMEM_BYTES 202752

// idesc: F32 acc (1<<4), bf16 a (1<<7), bf16 b (1<<10); all K-major
#define IDESC_S ((1u<<4)|(1u<<7)|(1u<<10)|((128/8)<<17)|((128/16)<<24))
#define IDESC_O ((1u<<4)|(1u<<7)|(1u<<10)|((64/8)<<17)|((128/16)<<24))
#define IDESC_L ((1u<<4)|(1u<<7)|(1u<<10)|((16/8)<<17)|((128/16)<<24))

// K-major SW128 descriptor (layout=2, ver=1, SBO=64, LBO=1) — validated
#define DESC_K  ((uint64_t(2)<<61)|(uint64_t(1)<<46)|(uint64_t(64)<<32)|(uint64_t(1)<<16))
#define MAKE_DESC(a) (DESC_K | ((uint64_t)((a) >> 4) & 0x3FFF))

__device__ float g_linv[BHh * Ss];

__device__ __forceinline__ uint32_t smem_u32(const void* p) {
    uint32_t a;
    asm("{ .reg .u64 t; cvta.to.shared.u64 t, %1; cvt.u32.u64 %0, t; }" : "=r"(a) : "l"(p));
    return a;
}
__device__ __forceinline__ uint32_t sw128(uint32_t x) { return x ^ ((x >> 3) & 0x70); }

#if USE_TC
__device__ __forceinline__ uint32_t elect_one() {
    uint32_t pred;
    asm volatile("{\n\t.reg .pred p;\n\telect.sync _|p, 0xFFFFFFFF;\n\tselp.b32 %0, 1, 0, p;\n\t}"
                 : "=r"(pred));
    return pred;
}
__device__ __forceinline__ float fexp2(float x) {
    float r;
    asm("ex2.approx.f32 %0, %1;" : "=f"(r) : "f"(x));
    return r;
}
__device__ __forceinline__ uint32_t pack_bf16(float lo, float hi) {
    uint32_t r;
    asm("cvt.rn.bf16x2.f32 %0, %1, %2;" : "=r"(r) : "f"(hi), "f"(lo));
    return r;
}
__device__ __forceinline__ float lofl(uint32_t u) { return __uint_as_float(u << 16); }
__device__ __forceinline__ float hifl(uint32_t u) { return __uint_as_float(u & 0xffff0000u); }

#define MBAR_INIT(addr, cnt) \
    asm volatile("mbarrier.init.shared.b64 [%0], %1;" :: "r"(addr), "r"(cnt) : "memory")
#define MBAR_INVAL(addr) \
    asm volatile("mbarrier.inval.shared.b64 [%0];" :: "r"(addr) : "memory")
#define MBAR_WAIT(addr, parity) do { \
    uint32_t _m = (uint32_t)(addr); uint32_t _p = (uint32_t)(parity); uint32_t _d; \
    asm volatile("{\n\t.reg .pred p;\n\t" \
        "mbarrier.try_wait.parity.acquire.cta.shared::cta.b64 p, [%1], %2;\n\t" \
        "selp.b32 %0, 1, 0, p;\n\t}" : "=r"(_d) : "r"(_m), "r"(_p) : "memory"); \
    if (!_d) { \
        asm volatile("{\n\t.reg .pred P1;\n\t" \
            "WL_%=:\n\t" \
            "mbarrier.try_wait.parity.acquire.cta.shared::cta.b64 P1, [%0], %1, 0x989680;\n\t" \
            "@P1 bra.uni WD_%=;\n\t" \
            "bra.uni WL_%=;\n\t" \
            "WD_%=:\n\t}" :: "r"(_m), "r"(_p) : "memory"); \
    } \
} while (0)

#define TC_ALLOC(smem_addr, ncols) \
    asm volatile("tcgen05.alloc.cta_group::1.sync.aligned.shared::cta.b32 [%0], %1;" \
                 :: "r"((uint32_t)(smem_addr)), "r"((uint32_t)(ncols)) : "memory")
#define TC_DEALLOC(tmem, ncols) \
    asm volatile("tcgen05.dealloc.cta_group::1.sync.aligned.b32 %0, %1;" \
                 :: "r"(tmem), "r"((uint32_t)(ncols)))
#define TC_RELINQ() \
    asm volatile("tcgen05.relinquish_alloc_permit.cta_group::1.sync.aligned;")
#define TC_COMMIT(mbar) \
    asm volatile("tcgen05.commit.cta_group::1.mbarrier::arrive::one.shared::cluster.b64 [%0];" \
                 :: "r"((uint32_t)(mbar)) : "memory")
#define TC_FENCE_BEFORE() asm volatile("tcgen05.fence::before_thread_sync;" ::: "memory")
#define TC_FENCE_AFTER()  asm volatile("tcgen05.fence::after_thread_sync;" ::: "memory")
#define TC_WAIT_LD() asm volatile("tcgen05.wait::ld.sync.aligned;" ::: "memory")
#define FENCE_ASYNC_SHARED() asm volatile("fence.proxy.async.shared::cta;" ::: "memory")

#define TC_LD_X32(r, addr) \
    asm volatile("tcgen05.ld.sync.aligned.32x32b.x32.b32 " \
        "{%0, %1, %2, %3, %4, %5, %6, %7, " \
        " %8, %9, %10, %11, %12, %13, %14, %15, " \
        " %16, %17, %18, %19, %20, %21, %22, %23, " \
        " %24, %25, %26, %27, %28, %29, %30, %31}, [%32];" \
        : "=r"((r)[0]),  "=r"((r)[1]),  "=r"((r)[2]),  "=r"((r)[3]), \
          "=r"((r)[4]),  "=r"((r)[5]),  "=r"((r)[6]),  "=r"((r)[7]), \
          "=r"((r)[8]),  "=r"((r)[9]),  "=r"((r)[10]), "=r"((r)[11]), \
          "=r"((r)[12]), "=r"((r)[13]), "=r"((r)[14]), "=r"((r)[15]), \
          "=r"((r)[16]), "=r"((r)[17]), "=r"((r)[18]), "=r"((r)[19]), \
          "=r"((r)[20]), "=r"((r)[21]), "=r"((r)[22]), "=r"((r)[23]), \
          "=r"((r)[24]), "=r"((r)[25]), "=r"((r)[26]), "=r"((r)[27]), \
          "=r"((r)[28]), "=r"((r)[29]), "=r"((r)[30]), "=r"((r)[31]) \
        : "r"(addr))
#define TC_LD_X1(r0, addr) \
    asm volatile("tcgen05.ld.sync.aligned.32x32b.x1.b32 {%0}, [%1];" : "=r"(r0) : "r"(addr))

__device__ __forceinline__ void mma_bf16(uint32_t d, uint64_t a, uint64_t b,
                                         uint32_t idesc, uint32_t acc) {
    asm volatile("{\n\t.reg .pred p;\n\tsetp.ne.u32 p, %5, 0;\n\t"
                 "tcgen05.mma.cta_group::1.kind::f16 [%0], %1, %2, %3, {%4, %4, %4, %4}, p;\n\t}"
                 :: "r"(d), "l"(a), "l"(b), "r"(idesc), "r"(0u), "r"(acc) : "memory");
}

__device__ __forceinline__ void split8(const float* x, uint4& H, uint4& L) {
    H.x = pack_bf16(x[0], x[1]); H.y = pack_bf16(x[2], x[3]);
    H.z = pack_bf16(x[4], x[5]); H.w = pack_bf16(x[6], x[7]);
    L.x = pack_bf16(x[0] - lofl(H.x), x[1] - hifl(H.x));
    L.y = pack_bf16(x[2] - lofl(H.y), x[3] - hifl(H.y));
    L.z = pack_bf16(x[4] - lofl(H.z), x[5] - hifl(H.z));
    L.w = pack_bf16(x[6] - lofl(H.w), x[7] - hifl(H.w));
}

// 512 threads: thread handles row t>>2, 16 cols starting (t&3)*16
__device__ __forceinline__ void ldg_tile(const float* __restrict__ src, float4* f, int t) {
    const float* p = src + (size_t)(t >> 2) * (Hh * Dd) + (t & 3) * 16;
#pragma unroll
    for (int j = 0; j < 4; j++) f[j] = *(const float4*)(p + 4 * j);
}

// bf16-split + store swizzled K-major (128 rows x 64 bf16)
__device__ __forceinline__ void sts_tile(const float4* f, uint32_t sbp,
                                         uint32_t off_hi, uint32_t off_lo,
                                         float scale, int t) {
    const int r = t >> 2, c0 = (t & 3) * 16;
    const uint32_t rowbase = ((uint32_t)(r >> 3) << 10) + ((uint32_t)(r & 7) << 7);
#pragma unroll
    for (int c = 0; c < 2; c++) {
        float x[8];
        const float4 a = f[2 * c], b = f[2 * c + 1];
        x[0] = a.x * scale; x[1] = a.y * scale; x[2] = a.z * scale; x[3] = a.w * scale;
        x[4] = b.x * scale; x[5] = b.y * scale; x[6] = b.z * scale; x[7] = b.w * scale;
        uint4 H, L;
        split8(x, H, L);
        uint32_t ad = sw128(rowbase + (uint32_t)(c0 + 8 * c) * 2);
        asm volatile("st.shared.v4.b32 [%0], {%1,%2,%3,%4};"
                     :: "r"(sbp + off_hi + ad), "r"(H.x), "r"(H.y), "r"(H.z), "r"(H.w));
        asm volatile("st.shared.v4.b32 [%0], {%1,%2,%3,%4};"
                     :: "r"(sbp + off_lo + ad), "r"(L.x), "r"(L.y), "r"(L.z), "r"(L.w));
    }
}

// bf16-split V + store TRANSPOSED V^T [64 d rows x 128 token cols] K-major (validated geometry)
__device__ __forceinline__ void sts_vt(const float4* f, uint32_t sbp,
                                       uint32_t off_hi, uint32_t off_lo, int t) {
    const int tok = t >> 2, c0 = (t & 3) * 16;
    const uint32_t tokpart = ((uint32_t)(tok >> 6) << 13) + ((uint32_t)(tok & 63) << 1);
    const float* x = (const float*)f;
#pragma unroll
    for (int j = 0; j < 16; j++) {
        const int d = c0 + j;
        float val = x[j];
        uint16_t hb;
        asm("cvt.rn.bf16.f32 %0, %1;" : "=h"(hb) : "f"(val));
        float hf = __uint_as_float((uint32_t)hb << 16);
        uint16_t lb;
        asm("cvt.rn.bf16.f32 %0, %1;" : "=h"(lb) : "f"(val - hf));
        uint32_t ad = sw128(((uint32_t)(d >> 3) << 10) + ((uint32_t)(d & 7) << 7) + tokpart);
        asm volatile("st.shared.b16 [%0], %1;" :: "r"(sbp + off_hi + ad), "h"(hb));
        asm volatile("st.shared.b16 [%0], %1;" :: "r"(sbp + off_lo + ad), "h"(lb));
    }
}
#endif  // USE_TC

__global__ __launch_bounds__(NTHR, 1) __cluster_dims__(1, 1, 1)
void attn_pass1_tc(const float* __restrict__ q, const float* __restrict__ k,
                   const float* __restrict__ v, float* __restrict__ out,
                   float* __restrict__ attn) {
    extern __shared__ char sm[];
    const int t = threadIdx.x;
    const int w = t >> 5, lid = t & 31;
    const int bh = blockIdx.y, b = bh >> 4, h = bh & 15;
    const int qt = (NQT - 1) - blockIdx.x;  // big tiles first
    const int qr0 = qt * TM;

    const float* qb = q + (size_t)b * Ss * Hh * Dd + (size_t)h * Dd;
    const float* kb = k + (size_t)b * Ss * Hh * Dd + (size_t)h * Dd;
    const float* vb = v + (size_t)b * Ss * Hh * Dd + (size_t)h * Dd;
    float* attnb = attn + (size_t)bh * Ss * Ss;

#if USE_TC
    // ====== tcgen05: S^T(2-buf TMEM) = K·Q^T, O = P·V^T, L = P·1, pipelined ======
    const uint32_t sb = smem_u32(sm);

    if (w == 0) TC_ALLOC(sb + SMEM_TMEMPTR, 512);
    if (t == 0) {
        MBAR_INIT(sb + SMEM_MBAR_S, 1);
        MBAR_INIT(sb + SMEM_MBAR_PV, 1);
    }
    for (int i = t; i < 1024; i += NTHR)
        ((uint32_t*)(sm + OFF_ONES))[i] = 0x3F803F80u;
    {
        float4 f[4];
        ldg_tile(qb + (size_t)qr0 * (Hh * Dd), f, t);
        sts_tile(f, sb, OFF_QHI, OFF_QLO, SCALE_Q, t);
        ldg_tile(kb, f, t);
        sts_tile(f, sb, OFF_KHI, OFF_KLO, 1.0f, t);
        ldg_tile(vb, f, t);
        sts_vt(f, sb, OFF_VTH0, OFF_VTL0, t);
    }
    FENCE_ASYNC_SHARED();
    __syncthreads();

    uint32_t tmem;
    asm volatile("ld.shared.b32 %0, [%1];" : "=r"(tmem) : "r"(sb + SMEM_TMEMPTR));
    const uint32_t ST_T[2] = {tmem, tmem + 128};  // double-buffered S^T
    const uint32_t O_T = tmem + 256;              // O: 64 cols, lanes = q rows
    const uint32_t L_T = tmem + 320;              // row sums: 16 cols

    const uint64_t dq_hi = MAKE_DESC(sb + OFF_QHI);
    const uint64_t dq_lo = MAKE_DESC(sb + OFF_QLO);
    const uint64_t dk_hi = MAKE_DESC(sb + OFF_KHI);
    const uint64_t dk_lo = MAKE_DESC(sb + OFF_KLO);
    const uint64_t dvh[2] = {MAKE_DESC(sb + OFF_VTH0), MAKE_DESC(sb + OFF_VTH1)};
    const uint64_t dvl[2] = {MAKE_DESC(sb + OFF_VTL0), MAKE_DESC(sb + OFF_VTL1)};
    const uint64_t dp_hi = MAKE_DESC(sb + OFF_PHI);
    const uint64_t dp_lo = MAKE_DESC(sb + OFF_PLO);
    const uint64_t dones = MAKE_DESC(sb + OFF_ONES);

    // S^T(0) into ST[0]
    if (w == 0 && elect_one()) {
#pragma unroll
        for (int kc = 0; kc < 4; kc++) {
            uint64_t o = (uint64_t)(kc << 1);
            mma_bf16(ST_T[0], dk_hi + o, dq_hi + o, IDESC_S, kc > 0);
            mma_bf16(ST_T[0], dk_hi + o, dq_lo + o, IDESC_S, 1);
            mma_bf16(ST_T[0], dk_lo + o, dq_hi + o, IDESC_S, 1);
        }
        TC_COMMIT(sb + SMEM_MBAR_S);
    }

    float4 fk[4], fv[4];
    if (qt >= 1) {
        ldg_tile(kb + (size_t)TN * (Hh * Dd), fk, t);
        ldg_tile(vb + (size_t)TN * (Hh * Dd), fv, t);
    }

    const int sp = w & 3;
    const int ch = (w >> 2) * 32;          // 32 q-columns per warp (16 warps)
    const int mk = sp * 32 + lid;          // TMEM lane (k token)
    const uint32_t colpart = ((uint32_t)(mk >> 6) << 14) + ((uint32_t)(mk & 63) << 1);
    int s_ph = 0, pv_ph = 0;

    for (int kt = 0; kt <= qt; kt++) {
        const int kc0 = kt * TN;
        const int cur = kt & 1, nxt = cur ^ 1;
        const bool diag = (kt == qt);

        // 1. wait S(kt) — hidden by prior epilogue once pipeline is primed
        MBAR_WAIT(sb + SMEM_MBAR_S, s_ph);
        s_ph ^= 1;
        TC_FENCE_AFTER();

        // 2. store K(kt+1) (K(kt) smem free now) and launch S(kt+1) into other buffer
        if (kt < qt) {
            sts_tile(fk, sb, OFF_KHI, OFF_KLO, 1.0f, t);
            FENCE_ASYNC_SHARED();
            __syncthreads();
            if (w == 0 && elect_one()) {
#pragma unroll
                for (int kc = 0; kc < 4; kc++) {
                    uint64_t o = (uint64_t)(kc << 1);
                    mma_bf16(ST_T[nxt], dk_hi + o, dq_hi + o, IDESC_S, kc > 0);
                    mma_bf16(ST_T[nxt], dk_hi + o, dq_lo + o, IDESC_S, 1);
                    mma_bf16(ST_T[nxt], dk_lo + o, dq_hi + o, IDESC_S, 1);
                }
                TC_COMMIT(sb + SMEM_MBAR_S);
            }
        }
        // 3. prefetch K(kt+2)
        if (kt + 2 <= qt) ldg_tile(kb + (size_t)(kc0 + 2 * TN) * (Hh * Dd), fk, t);

        // 4. epilogue on ST[cur]: exp, mask, attn STG (coalesced)
        uint32_t r[32];
        TC_LD_X32(r, ST_T[cur] + ch);
        TC_WAIT_LD();
        {
            float* arow = attnb + (size_t)(qr0 + ch) * Ss + kc0 + mk;
#pragma unroll
            for (int j = 0; j < 32; j++) {
                const int ql = ch + j;
                float ev = fexp2(__uint_as_float(r[j]));
                if (diag && (mk > ql)) ev = 0.f;
                arow[(size_t)j * Ss] = ev;
                r[j] = __float_as_uint(ev);
            }
        }
        // 5. PV(kt-1) must finish before P smem is overwritten
        if (kt > 0) { MBAR_WAIT(sb + SMEM_MBAR_PV, pv_ph); pv_ph ^= 1; }
        // 6. stage P hi/lo (bf16 split)
#pragma unroll
        for (int j = 0; j < 32; j++) {
            const int ql = ch + j;
            float ev = __uint_as_float(r[j]);
            uint16_t hb;
            asm("cvt.rn.bf16.f32 %0, %1;" : "=h"(hb) : "f"(ev));
            float hf = __uint_as_float((uint32_t)hb << 16);
            uint16_t lb;
            asm("cvt.rn.bf16.f32 %0, %1;" : "=h"(lb) : "f"(ev - hf));
            uint32_t ad = sw128(((uint32_t)(ql >> 3) << 10) +
                                ((uint32_t)(ql & 7) << 7) + colpart);
            asm volatile("st.shared.b16 [%0], %1;" :: "r"(sb + OFF_PHI + ad), "h"(hb));
            asm volatile("st.shared.b16 [%0], %1;" :: "r"(sb + OFF_PLO + ad), "h"(lb));
        }
        // 7. store V(kt+1) into buffer nxt (PV(kt-1) done reading it), prefetch V(kt+2)
        if (kt < qt) {
            const uint32_t vh = nxt ? OFF_VTH1 : OFF_VTH0;
            const uint32_t vl = nxt ? OFF_VTL1 : OFF_VTL0;
            sts_vt(fv, sb, vh, vl, t);
            if (kt + 2 <= qt) ldg_tile(vb + (size_t)(kc0 + 2 * TN) * (Hh * Dd), fv, t);
        }
        TC_FENCE_BEFORE();
        FENCE_ASYNC_SHARED();
        __syncthreads();

        // 8. O += P·V^T(buf cur), L += P·1, commit
        if (w == 0 && elect_one()) {
#pragma unroll
            for (int kc = 0; kc < 8; kc++) {
                uint64_t oa = (uint64_t)(((kc >> 2) << 10) + ((kc & 3) << 1));
                uint64_t ob = (uint64_t)(((kc >> 2) << 9) + ((kc & 3) << 1));
                mma_bf16(O_T, dp_hi + oa, dvh[cur] + ob, IDESC_O, !(kt == 0 && kc == 0));
                mma_bf16(O_T, dp_hi + oa, dvl[cur] + ob, IDESC_O, 1);
                mma_bf16(O_T, dp_lo + oa, dvh[cur] + ob, IDESC_O, 1);
            }
#pragma unroll
            for (int kc = 0; kc < 8; kc++) {
                uint64_t oa = (uint64_t)(((kc >> 2) << 10) + ((kc & 3) << 1));
                uint64_t oo = (uint64_t)(((kc >> 2) << 7) + ((kc & 3) << 1));
                mma_bf16(L_T, dp_hi + oa, dones + oo, IDESC_L, !(kt == 0 && kc == 0));
                mma_bf16(L_T, dp_lo + oa, dones + oo, IDESC_L, 1);
            }
            TC_COMMIT(sb + SMEM_MBAR_PV);
        }
    }

    // zero-fill masked (strictly upper) region of attn (overlaps last PV)
    {
        const int zc0 = (qt + 1) * TN;
        const float4 z = make_float4(0.f, 0.f, 0.f, 0.f);
        for (int rr = w; rr < TM; rr += 16) {
            float* rowp = attnb + (size_t)(qr0 + rr) * Ss;
            for (int c = zc0 + lid * 4; c < Ss; c += 128)
                *(float4*)(rowp + c) = z;
        }
    }

    // final: wait last PV, read L and O (lanes = q rows), normalize, store
    MBAR_WAIT(sb + SMEM_MBAR_PV, pv_ph);
    TC_FENCE_AFTER();
    if (w < 8) {
        const int m = (w & 3) * 32 + lid;   // q row
        uint32_t lr;
        TC_LD_X1(lr, L_T);
        uint32_t r[32];
        TC_LD_X32(r, O_T + (w >> 2) * 32);
        TC_WAIT_LD();
        const float inv = 1.0f / __uint_as_float(lr);
        if (w < 4) g_linv[bh * Ss + qr0 + m] = inv;
        float* op = out + (size_t)b * Ss * Hh * Dd + (size_t)(qr0 + m) * (Hh * Dd) +
                    h * Dd + (w >> 2) * 32;
#pragma unroll
        for (int j = 0; j < 32; j += 4) {
            float4 o4 = make_float4(__uint_as_float(r[j]) * inv,
                                    __uint_as_float(r[j + 1]) * inv,
                                    __uint_as_float(r[j + 2]) * inv,
                                    __uint_as_float(r[j + 3]) * inv);
            *(float4*)(op + j) = o4;
        }
        TC_FENCE_BEFORE();
    }
    __syncthreads();
    if (t == 0) { MBAR_INVAL(sb + SMEM_MBAR_S); MBAR_INVAL(sb + SMEM_MBAR_PV); }
    __syncthreads();
    if (w == 0) {
        TC_RELINQ();
        TC_DEALLOC(tmem, 512);
    }
#else
    // ============== correct (slow) fallback for the plain-sm_103 pass ==============
    float* opart = (float*)sm;              // [4][128][64]
    float* lpart = (float*)(sm + 131072);   // [4][128]
    const int rl = t >> 2;                  // local row 0..127
    const int r = qr0 + rl;
    const int qd = t & 3;
    const float* qrow = qb + (size_t)r * (Hh * Dd);
    float qreg[64];
#pragma unroll
    for (int d = 0; d < 64; d++) qreg[d] = qrow[d] * 0.125f;
    float o[64];
#pragma unroll
    for (int d = 0; d < 64; d++) o[d] = 0.f;
    float ls = 0.f;
    for (int kk = qd; kk <= r; kk += 4) {
        const float* krow = kb + (size_t)kk * (Hh * Dd);
        float s = 0.f;
#pragma unroll
        for (int d = 0; d < 64; d++) s += qreg[d] * krow[d];
        float e = __expf(s);
        attnb[(size_t)r * Ss + kk] = e;
        ls += e;
        const float* vrow = vb + (size_t)kk * (Hh * Dd);
#pragma unroll
        for (int d = 0; d < 64; d++) o[d] += e * vrow[d];
    }
#pragma unroll
    for (int d = 0; d < 64; d++) opart[((qd << 7) + rl) * 64 + d] = o[d];
    lpart[(qd << 7) + rl] = ls;
    // zero-fill masked region for this row
    for (int c = r + 1 + qd; c < Ss; c += 4) attnb[(size_t)r * Ss + c] = 0.f;
    __syncthreads();
    if (qd == 0) {
        float tot = lpart[rl] + lpart[128 + rl] + lpart[256 + rl] + lpart[384 + rl];
        float inv = 1.0f / tot;
        g_linv[bh * Ss + r] = inv;
        float* op = out + (size_t)b * Ss * Hh * Dd + (size_t)r * (Hh * Dd) + h * Dd;
        for (int d = 0; d < 64; d++) {
            float s = opart[rl * 64 + d] + opart[(128 + rl) * 64 + d] +
                      opart[(256 + rl) * 64 + d] + opart[(384 + rl) * 64 + d];
            op[d] = s * inv;
        }
    }
#endif
}

// Normalize the causal prefix. Pair row j with row 2047-j for load balance.
__global__ __launch_bounds__(256) void attn_norm2(float* __restrict__ attn) {
    const int x = blockIdx.x;
    const int bh = x >> 10;
    const int jl = x & 1023;
    float* base = attn + (size_t)bh * Ss * Ss;
#pragma unroll
    for (int which = 0; which < 2; which++) {
        const int row = which ? (Ss - 1 - jl) : jl;
        const float inv = g_linv[bh * Ss + row];
        const int n4 = (row + 4) >> 2;
        float4* p = (float4*)(base + (size_t)row * Ss);
        for (int c = threadIdx.x; c < n4; c += 256) {
            float4 u = p[c];
            u.x *= inv; u.y *= inv; u.z *= inv; u.w *= inv;
            p[c] = u;
        }
    }
}

extern "C" void kernel_launch(void* const* d_in, const int* in_sizes, int n_in,
                              void* d_out, int out_size) {
    const float* q = (const float*)d_in[0];
    const float* k = (const float*)d_in[1];
    const float* v = (const float*)d_in[2];
    // d_in[3] = causal mask (deterministic triu) -> handled analytically

    float* out = (float*)d_out;
    float* attn = (float*)d_out + (size_t)Bb * Ss * Hh * Dd;

    cudaFuncSetAttribute(attn_pass1_tc, cudaFuncAttributeMaxDynamicSharedMemorySize,
                         SMEM_BYTES);

    dim3 grid(NQT, BHh);
    attn_pass1_tc<<<grid, NTHR, SMEM_BYTES>>>(q, k, v, out, attn);
    attn_norm2<<<BHh * 1024, 256>>>(attn);
}

// round 8
// speedup vs baseline: 1.1258x; 1.0671x over previous
#include <cuda_runtime.h>
#include <cstdint>

#define Bb 4
#define Ss 2048
#define Hh 16
#define BHh 64
#define Dd 64
#define TM 128
#define TN 128
#define NQT 16
#define NTHR 512
#define SCALE_Q 0.1803368801111204f  /* log2(e)/8 */

// tcgen05 exists only on arch-specific sm_10Xa targets.
#if defined(__CUDA_ARCH__) && (defined(__CUDA_ARCH_FEAT_SM103_ALL) || \
    defined(__CUDA_ARCH_FEAT_SM100_ALL) || defined(__CUDA_ARCH_FEAT_SM101_ALL))
#define USE_TC 1
#else
#define USE_TC 0
#endif

// ---------------- SMEM map (tcgen05 path, all tiles 1024-aligned) ----------------
#define SMEM_TMEMPTR 0
#define SMEM_MBAR_S 64
#define SMEM_MBAR_PV 72
#define SMEM_INV 128            /* 128 floats: per-row 1/L */
#define OFF_QHI 2048
#define OFF_QLO 18432
#define OFF_KHI 34816
#define OFF_KLO 51200
#define OFF_VTH0 67584
#define OFF_VTL0 83968
#define OFF_VTH1 100352
#define OFF_VTL1 116736
#define OFF_PHI 133120
#define OFF_PLO 165888
#define OFF_ONES 198656
#define SMEM_BYTES 202752

// idesc: F32 acc (1<<4), bf16 a (1<<7), bf16 b (1<<10); all K-major
#define IDESC_S ((1u<<4)|(1u<<7)|(1u<<10)|((128/8)<<17)|((128/16)<<24))
#define IDESC_O ((1u<<4)|(1u<<7)|(1u<<10)|((64/8)<<17)|((128/16)<<24))
#define IDESC_L ((1u<<4)|(1u<<7)|(1u<<10)|((16/8)<<17)|((128/16)<<24))

// K-major SW128 descriptor (layout=2, ver=1, SBO=64, LBO=1) — validated
#define DESC_K  ((uint64_t(2)<<61)|(uint64_t(1)<<46)|(uint64_t(64)<<32)|(uint64_t(1)<<16))
#define MAKE_DESC(a) (DESC_K | ((uint64_t)((a) >> 4) & 0x3FFF))

__device__ __forceinline__ uint32_t smem_u32(const void* p) {
    uint32_t a;
    asm("{ .reg .u64 t; cvta.to.shared.u64 t, %1; cvt.u32.u64 %0, t; }" : "=r"(a) : "l"(p));
    return a;
}
__device__ __forceinline__ uint32_t sw128(uint32_t x) { return x ^ ((x >> 3) & 0x70); }

#if USE_TC
__device__ __forceinline__ uint32_t elect_one() {
    uint32_t pred;
    asm volatile("{\n\t.reg .pred p;\n\telect.sync _|p, 0xFFFFFFFF;\n\tselp.b32 %0, 1, 0, p;\n\t}"
                 : "=r"(pred));
    return pred;
}
__device__ __forceinline__ float fexp2(float x) {
    float r;
    asm("ex2.approx.f32 %0, %1;" : "=f"(r) : "f"(x));
    return r;
}
__device__ __forceinline__ uint32_t pack_bf16(float lo, float hi) {
    uint32_t r;
    asm("cvt.rn.bf16x2.f32 %0, %1, %2;" : "=r"(r) : "f"(hi), "f"(lo));
    return r;
}
__device__ __forceinline__ float lofl(uint32_t u) { return __uint_as_float(u << 16); }
__device__ __forceinline__ float hifl(uint32_t u) { return __uint_as_float(u & 0xffff0000u); }

#define MBAR_INIT(addr, cnt) \
    asm volatile("mbarrier.init.shared.b64 [%0], %1;" :: "r"(addr), "r"(cnt) : "memory")
#define MBAR_INVAL(addr) \
    asm volatile("mbarrier.inval.shared.b64 [%0];" :: "r"(addr) : "memory")
#define MBAR_WAIT(addr, parity) do { \
    uint32_t _m = (uint32_t)(addr); uint32_t _p = (uint32_t)(parity); uint32_t _d; \
    asm volatile("{\n\t.reg .pred p;\n\t" \
        "mbarrier.try_wait.parity.acquire.cta.shared::cta.b64 p, [%1], %2;\n\t" \
        "selp.b32 %0, 1, 0, p;\n\t}" : "=r"(_d) : "r"(_m), "r"(_p) : "memory"); \
    if (!_d) { \
        asm volatile("{\n\t.reg .pred P1;\n\t" \
            "WL_%=:\n\t" \
            "mbarrier.try_wait.parity.acquire.cta.shared::cta.b64 P1, [%0], %1, 0x989680;\n\t" \
            "@P1 bra.uni WD_%=;\n\t" \
            "bra.uni WL_%=;\n\t" \
            "WD_%=:\n\t}" :: "r"(_m), "r"(_p) : "memory"); \
    } \
} while (0)

#define TC_ALLOC(smem_addr, ncols) \
    asm volatile("tcgen05.alloc.cta_group::1.sync.aligned.shared::cta.b32 [%0], %1;" \
                 :: "r"((uint32_t)(smem_addr)), "r"((uint32_t)(ncols)) : "memory")
#define TC_DEALLOC(tmem, ncols) \
    asm volatile("tcgen05.dealloc.cta_group::1.sync.aligned.b32 %0, %1;" \
                 :: "r"(tmem), "r"((uint32_t)(ncols)))
#define TC_RELINQ() \
    asm volatile("tcgen05.relinquish_alloc_permit.cta_group::1.sync.aligned;")
#define TC_COMMIT(mbar) \
    asm volatile("tcgen05.commit.cta_group::1.mbarrier::arrive::one.shared::cluster.b64 [%0];" \
                 :: "r"((uint32_t)(mbar)) : "memory")
#define TC_FENCE_BEFORE() asm volatile("tcgen05.fence::before_thread_sync;" ::: "memory")
#define TC_FENCE_AFTER()  asm volatile("tcgen05.fence::after_thread_sync;" ::: "memory")
#define TC_WAIT_LD() asm volatile("tcgen05.wait::ld.sync.aligned;" ::: "memory")
#define FENCE_ASYNC_SHARED() asm volatile("fence.proxy.async.shared::cta;" ::: "memory")

#define TC_LD_X32(r, addr) \
    asm volatile("tcgen05.ld.sync.aligned.32x32b.x32.b32 " \
        "{%0, %1, %2, %3, %4, %5, %6, %7, " \
        " %8, %9, %10, %11, %12, %13, %14, %15, " \
        " %16, %17, %18, %19, %20, %21, %22, %23, " \
        " %24, %25, %26, %27, %28, %29, %30, %31}, [%32];" \
        : "=r"((r)[0]),  "=r"((r)[1]),  "=r"((r)[2]),  "=r"((r)[3]), \
          "=r"((r)[4]),  "=r"((r)[5]),  "=r"((r)[6]),  "=r"((r)[7]), \
          "=r"((r)[8]),  "=r"((r)[9]),  "=r"((r)[10]), "=r"((r)[11]), \
          "=r"((r)[12]), "=r"((r)[13]), "=r"((r)[14]), "=r"((r)[15]), \
          "=r"((r)[16]), "=r"((r)[17]), "=r"((r)[18]), "=r"((r)[19]), \
          "=r"((r)[20]), "=r"((r)[21]), "=r"((r)[22]), "=r"((r)[23]), \
          "=r"((r)[24]), "=r"((r)[25]), "=r"((r)[26]), "=r"((r)[27]), \
          "=r"((r)[28]), "=r"((r)[29]), "=r"((r)[30]), "=r"((r)[31]) \
        : "r"(addr))
#define TC_LD_X1(r0, addr) \
    asm volatile("tcgen05.ld.sync.aligned.32x32b.x1.b32 {%0}, [%1];" : "=r"(r0) : "r"(addr))

__device__ __forceinline__ void mma_bf16(uint32_t d, uint64_t a, uint64_t b,
                                         uint32_t idesc, uint32_t acc) {
    asm volatile("{\n\t.reg .pred p;\n\tsetp.ne.u32 p, %5, 0;\n\t"
                 "tcgen05.mma.cta_group::1.kind::f16 [%0], %1, %2, %3, {%4, %4, %4, %4}, p;\n\t}"
                 :: "r"(d), "l"(a), "l"(b), "r"(idesc), "r"(0u), "r"(acc) : "memory");
}

__device__ __forceinline__ void split8(const float* x, uint4& H, uint4& L) {
    H.x = pack_bf16(x[0], x[1]); H.y = pack_bf16(x[2], x[3]);
    H.z = pack_bf16(x[4], x[5]); H.w = pack_bf16(x[6], x[7]);
    L.x = pack_bf16(x[0] - lofl(H.x), x[1] - hifl(H.x));
    L.y = pack_bf16(x[2] - lofl(H.y), x[3] - hifl(H.y));
    L.z = pack_bf16(x[4] - lofl(H.z), x[5] - hifl(H.z));
    L.w = pack_bf16(x[6] - lofl(H.w), x[7] - hifl(H.w));
}

// 512 threads: thread handles row t>>2, 16 cols starting (t&3)*16
__device__ __forceinline__ void ldg_tile(const float* __restrict__ src, float4* f, int t) {
    const float* p = src + (size_t)(t >> 2) * (Hh * Dd) + (t & 3) * 16;
#pragma unroll
    for (int j = 0; j < 4; j++) f[j] = *(const float4*)(p + 4 * j);
}

// bf16-split + store swizzled K-major (128 rows x 64 bf16)
__device__ __forceinline__ void sts_tile(const float4* f, uint32_t sbp,
                                         uint32_t off_hi, uint32_t off_lo,
                                         float scale, int t) {
    const int r = t >> 2, c0 = (t & 3) * 16;
    const uint32_t rowbase = ((uint32_t)(r >> 3) << 10) + ((uint32_t)(r & 7) << 7);
#pragma unroll
    for (int c = 0; c < 2; c++) {
        float x[8];
        const float4 a = f[2 * c], b = f[2 * c + 1];
        x[0] = a.x * scale; x[1] = a.y * scale; x[2] = a.z * scale; x[3] = a.w * scale;
        x[4] = b.x * scale; x[5] = b.y * scale; x[6] = b.z * scale; x[7] = b.w * scale;
        uint4 H, L;
        split8(x, H, L);
        uint32_t ad = sw128(rowbase + (uint32_t)(c0 + 8 * c) * 2);
        asm volatile("st.shared.v4.b32 [%0], {%1,%2,%3,%4};"
                     :: "r"(sbp + off_hi + ad), "r"(H.x), "r"(H.y), "r"(H.z), "r"(H.w));
        asm volatile("st.shared.v4.b32 [%0], {%1,%2,%3,%4};"
                     :: "r"(sbp + off_lo + ad), "r"(L.x), "r"(L.y), "r"(L.z), "r"(L.w));
    }
}

// bf16-split V + store TRANSPOSED V^T [64 d rows x 128 token cols] K-major (validated geometry)
__device__ __forceinline__ void sts_vt(const float4* f, uint32_t sbp,
                                       uint32_t off_hi, uint32_t off_lo, int t) {
    const int tok = t >> 2, c0 = (t & 3) * 16;
    const uint32_t tokpart = ((uint32_t)(tok >> 6) << 13) + ((uint32_t)(tok & 63) << 1);
    const float* x = (const float*)f;
#pragma unroll
    for (int j = 0; j < 16; j++) {
        const int d = c0 + j;
        float val = x[j];
        uint16_t hb;
        asm("cvt.rn.bf16.f32 %0, %1;" : "=h"(hb) : "f"(val));
        float hf = __uint_as_float((uint32_t)hb << 16);
        uint16_t lb;
        asm("cvt.rn.bf16.f32 %0, %1;" : "=h"(lb) : "f"(val - hf));
        uint32_t ad = sw128(((uint32_t)(d >> 3) << 10) + ((uint32_t)(d & 7) << 7) + tokpart);
        asm volatile("st.shared.b16 [%0], %1;" :: "r"(sbp + off_hi + ad), "h"(hb));
        asm volatile("st.shared.b16 [%0], %1;" :: "r"(sbp + off_lo + ad), "h"(lb));
    }
}
#endif  // USE_TC

__global__ __launch_bounds__(NTHR, 1) __cluster_dims__(1, 1, 1)
void attn_fused_tc(const float* __restrict__ q, const float* __restrict__ k,
                   const float* __restrict__ v, float* __restrict__ out,
                   float* __restrict__ attn) {
    extern __shared__ char sm[];
    const int t = threadIdx.x;
    const int w = t >> 5, lid = t & 31;
    const int bh = blockIdx.y, b = bh >> 4, h = bh & 15;
    const int qt = (NQT - 1) - blockIdx.x;  // big tiles first
    const int qr0 = qt * TM;

    const float* qb = q + (size_t)b * Ss * Hh * Dd + (size_t)h * Dd;
    const float* kb = k + (size_t)b * Ss * Hh * Dd + (size_t)h * Dd;
    const float* vb = v + (size_t)b * Ss * Hh * Dd + (size_t)h * Dd;
    float* attnb = attn + (size_t)bh * Ss * Ss;

#if USE_TC
    // ====== tcgen05: S^T(2-buf TMEM) = K·Q^T, O = P·V^T, L = P·1, fused norm ======
    const uint32_t sb = smem_u32(sm);

    if (w == 0) TC_ALLOC(sb + SMEM_TMEMPTR, 512);
    if (t == 0) {
        MBAR_INIT(sb + SMEM_MBAR_S, 1);
        MBAR_INIT(sb + SMEM_MBAR_PV, 1);
    }
    for (int i = t; i < 1024; i += NTHR)
        ((uint32_t*)(sm + OFF_ONES))[i] = 0x3F803F80u;
    {
        float4 f[4];
        ldg_tile(qb + (size_t)qr0 * (Hh * Dd), f, t);
        sts_tile(f, sb, OFF_QHI, OFF_QLO, SCALE_Q, t);
        ldg_tile(kb, f, t);
        sts_tile(f, sb, OFF_KHI, OFF_KLO, 1.0f, t);
        ldg_tile(vb, f, t);
        sts_vt(f, sb, OFF_VTH0, OFF_VTL0, t);
    }
    FENCE_ASYNC_SHARED();
    __syncthreads();

    uint32_t tmem;
    asm volatile("ld.shared.b32 %0, [%1];" : "=r"(tmem) : "r"(sb + SMEM_TMEMPTR));
    const uint32_t ST_T[2] = {tmem, tmem + 128};  // double-buffered S^T
    const uint32_t O_T = tmem + 256;              // O: 64 cols, lanes = q rows
    const uint32_t L_T = tmem + 320;              // row sums: 16 cols

    const uint64_t dq_hi = MAKE_DESC(sb + OFF_QHI);
    const uint64_t dq_lo = MAKE_DESC(sb + OFF_QLO);
    const uint64_t dk_hi = MAKE_DESC(sb + OFF_KHI);
    const uint64_t dk_lo = MAKE_DESC(sb + OFF_KLO);
    const uint64_t dvh[2] = {MAKE_DESC(sb + OFF_VTH0), MAKE_DESC(sb + OFF_VTH1)};
    const uint64_t dvl[2] = {MAKE_DESC(sb + OFF_VTL0), MAKE_DESC(sb + OFF_VTL1)};
    const uint64_t dp_hi = MAKE_DESC(sb + OFF_PHI);
    const uint64_t dp_lo = MAKE_DESC(sb + OFF_PLO);
    const uint64_t dones = MAKE_DESC(sb + OFF_ONES);

    // S^T(0) into ST[0]
    if (w == 0 && elect_one()) {
#pragma unroll
        for (int kc = 0; kc < 4; kc++) {
            uint64_t o = (uint64_t)(kc << 1);
            mma_bf16(ST_T[0], dk_hi + o, dq_hi + o, IDESC_S, kc > 0);
            mma_bf16(ST_T[0], dk_hi + o, dq_lo + o, IDESC_S, 1);
            mma_bf16(ST_T[0], dk_lo + o, dq_hi + o, IDESC_S, 1);
        }
        TC_COMMIT(sb + SMEM_MBAR_S);
    }

    float4 fk[4], fv[4];
    if (qt >= 1) {
        ldg_tile(kb + (size_t)TN * (Hh * Dd), fk, t);
        ldg_tile(vb + (size_t)TN * (Hh * Dd), fv, t);
    }

    const int sp = w & 3;
    const int ch = (w >> 2) * 32;          // 32 q-columns per warp (16 warps)
    const int mk = sp * 32 + lid;          // TMEM lane (k token)
    const uint32_t colpart = ((uint32_t)(mk >> 6) << 14) + ((uint32_t)(mk & 63) << 1);
    int s_ph = 0, pv_ph = 0;

    for (int kt = 0; kt <= qt; kt++) {
        const int kc0 = kt * TN;
        const int cur = kt & 1, nxt = cur ^ 1;
        const bool diag = (kt == qt);

        // 1. wait S(kt)
        MBAR_WAIT(sb + SMEM_MBAR_S, s_ph);
        s_ph ^= 1;
        TC_FENCE_AFTER();

        // 2. store K(kt+1), launch S(kt+1) into other buffer
        if (kt < qt) {
            sts_tile(fk, sb, OFF_KHI, OFF_KLO, 1.0f, t);
            FENCE_ASYNC_SHARED();
            __syncthreads();
            if (w == 0 && elect_one()) {
#pragma unroll
                for (int kc = 0; kc < 4; kc++) {
                    uint64_t o = (uint64_t)(kc << 1);
                    mma_bf16(ST_T[nxt], dk_hi + o, dq_hi + o, IDESC_S, kc > 0);
                    mma_bf16(ST_T[nxt], dk_hi + o, dq_lo + o, IDESC_S, 1);
                    mma_bf16(ST_T[nxt], dk_lo + o, dq_hi + o, IDESC_S, 1);
                }
                TC_COMMIT(sb + SMEM_MBAR_S);
            }
        }
        // 3. prefetch K(kt+2)
        if (kt + 2 <= qt) ldg_tile(kb + (size_t)(kc0 + 2 * TN) * (Hh * Dd), fk, t);

        // 4. epilogue on ST[cur]: exp, mask, attn STG (coalesced, unnormalized)
        uint32_t r[32];
        TC_LD_X32(r, ST_T[cur] + ch);
        TC_WAIT_LD();
        {
            float* arow = attnb + (size_t)(qr0 + ch) * Ss + kc0 + mk;
#pragma unroll
            for (int j = 0; j < 32; j++) {
                const int ql = ch + j;
                float ev = fexp2(__uint_as_float(r[j]));
                if (diag && (mk > ql)) ev = 0.f;
                arow[(size_t)j * Ss] = ev;
                r[j] = __float_as_uint(ev);
            }
        }
        // 5. PV(kt-1) must finish before P smem is overwritten
        if (kt > 0) { MBAR_WAIT(sb + SMEM_MBAR_PV, pv_ph); pv_ph ^= 1; }
        // 6. stage P hi/lo (bf16 split)
#pragma unroll
        for (int j = 0; j < 32; j++) {
            const int ql = ch + j;
            float ev = __uint_as_float(r[j]);
            uint16_t hb;
            asm("cvt.rn.bf16.f32 %0, %1;" : "=h"(hb) : "f"(ev));
            float hf = __uint_as_float((uint32_t)hb << 16);
            uint16_t lb;
            asm("cvt.rn.bf16.f32 %0, %1;" : "=h"(lb) : "f"(ev - hf));
            uint32_t ad = sw128(((uint32_t)(ql >> 3) << 10) +
                                ((uint32_t)(ql & 7) << 7) + colpart);
            asm volatile("st.shared.b16 [%0], %1;" :: "r"(sb + OFF_PHI + ad), "h"(hb));
            asm volatile("st.shared.b16 [%0], %1;" :: "r"(sb + OFF_PLO + ad), "h"(lb));
        }
        // 7. store V(kt+1) into buffer nxt, prefetch V(kt+2)
        if (kt < qt) {
            const uint32_t vh = nxt ? OFF_VTH1 : OFF_VTH0;
            const uint32_t vl = nxt ? OFF_VTL1 : OFF_VTL0;
            sts_vt(fv, sb, vh, vl, t);
            if (kt + 2 <= qt) ldg_tile(vb + (size_t)(kc0 + 2 * TN) * (Hh * Dd), fv, t);
        }
        TC_FENCE_BEFORE();
        FENCE_ASYNC_SHARED();
        __syncthreads();

        // 8. O += P·V^T(buf cur) [3-term split], L += P_hi·1, commit
        if (w == 0 && elect_one()) {
#pragma unroll
            for (int kc = 0; kc < 8; kc++) {
                uint64_t oa = (uint64_t)(((kc >> 2) << 10) + ((kc & 3) << 1));
                uint64_t ob = (uint64_t)(((kc >> 2) << 9) + ((kc & 3) << 1));
                mma_bf16(O_T, dp_hi + oa, dvh[cur] + ob, IDESC_O, !(kt == 0 && kc == 0));
                mma_bf16(O_T, dp_hi + oa, dvl[cur] + ob, IDESC_O, 1);
                mma_bf16(O_T, dp_lo + oa, dvh[cur] + ob, IDESC_O, 1);
            }
#pragma unroll
            for (int kc = 0; kc < 8; kc++) {
                uint64_t oa = (uint64_t)(((kc >> 2) << 10) + ((kc & 3) << 1));
                uint64_t oo = (uint64_t)(((kc >> 2) << 7) + ((kc & 3) << 1));
                mma_bf16(L_T, dp_hi + oa, dones + oo, IDESC_L, !(kt == 0 && kc == 0));
            }
            TC_COMMIT(sb + SMEM_MBAR_PV);
        }
    }

    // zero-fill masked (strictly upper) region of attn (overlaps last PV)
    {
        const int zc0 = (qt + 1) * TN;
        const float4 z = make_float4(0.f, 0.f, 0.f, 0.f);
        for (int rr = w; rr < TM; rr += 16) {
            float* rowp = attnb + (size_t)(qr0 + rr) * Ss;
            for (int c = zc0 + lid * 4; c < Ss; c += 128)
                *(float4*)(rowp + c) = z;
        }
    }

    // wait last PV, read L and O (lanes = q rows), store normalized O, stash inv
    MBAR_WAIT(sb + SMEM_MBAR_PV, pv_ph);
    TC_FENCE_AFTER();
    if (w < 8) {
        const int m = (w & 3) * 32 + lid;   // q row
        uint32_t lr;
        TC_LD_X1(lr, L_T);
        uint32_t r[32];
        TC_LD_X32(r, O_T + (w >> 2) * 32);
        TC_WAIT_LD();
        const float inv = 1.0f / __uint_as_float(lr);
        if (w < 4) ((float*)(sm + SMEM_INV))[m] = inv;
        float* op = out + (size_t)b * Ss * Hh * Dd + (size_t)(qr0 + m) * (Hh * Dd) +
                    h * Dd + (w >> 2) * 32;
#pragma unroll
        for (int j = 0; j < 32; j += 4) {
            float4 o4 = make_float4(__uint_as_float(r[j]) * inv,
                                    __uint_as_float(r[j + 1]) * inv,
                                    __uint_as_float(r[j + 2]) * inv,
                                    __uint_as_float(r[j + 3]) * inv);
            *(float4*)(op + j) = o4;
        }
        TC_FENCE_BEFORE();
    }
    __syncthreads();   // attn writes + inv visible CTA-wide

    // fused normalization: rescale this CTA's causal attn rows (likely L2-hot)
    {
        const int ncol4 = (qt + 1) * 32;   // float4s per row in the causal rectangle
        for (int rr = w * 8; rr < w * 8 + 8; rr++) {
            const float iv = ((float*)(sm + SMEM_INV))[rr];
            float4* rowp = (float4*)(attnb + (size_t)(qr0 + rr) * Ss);
            for (int c = lid; c < ncol4; c += 32) {
                float4 u = rowp[c];
                u.x *= iv; u.y *= iv; u.z *= iv; u.w *= iv;
                rowp[c] = u;
            }
        }
    }

    __syncthreads();
    if (t == 0) { MBAR_INVAL(sb + SMEM_MBAR_S); MBAR_INVAL(sb + SMEM_MBAR_PV); }
    __syncthreads();
    if (w == 0) {
        TC_RELINQ();
        TC_DEALLOC(tmem, 512);
    }
#else
    // ============== correct (slow) fallback for the plain-sm_103 pass ==============
    float* opart = (float*)sm;              // [4][128][64]
    float* lpart = (float*)(sm + 131072);   // [4][128]
    const int rl = t >> 2;                  // local row 0..127
    const int r = qr0 + rl;
    const int qd = t & 3;
    const float* qrow = qb + (size_t)r * (Hh * Dd);
    float qreg[64];
#pragma unroll
    for (int d = 0; d < 64; d++) qreg[d] = qrow[d] * 0.125f;
    float o[64];
#pragma unroll
    for (int d = 0; d < 64; d++) o[d] = 0.f;
    float ls = 0.f;
    for (int kk = qd; kk <= r; kk += 4) {
        const float* krow = kb + (size_t)kk * (Hh * Dd);
        float s = 0.f;
#pragma unroll
        for (int d = 0; d < 64; d++) s += qreg[d] * krow[d];
        float e = __expf(s);
        attnb[(size_t)r * Ss + kk] = e;
        ls += e;
        const float* vrow = vb + (size_t)kk * (Hh * Dd);
#pragma unroll
        for (int d = 0; d < 64; d++) o[d] += e * vrow[d];
    }
#pragma unroll
    for (int d = 0; d < 64; d++) opart[((qd << 7) + rl) * 64 + d] = o[d];
    lpart[(qd << 7) + rl] = ls;
    for (int c = r + 1 + qd; c < Ss; c += 4) attnb[(size_t)r * Ss + c] = 0.f;
    __syncthreads();
    float tot = lpart[rl] + lpart[128 + rl] + lpart[256 + rl] + lpart[384 + rl];
    float inv = 1.0f / tot;
    if (qd == 0) {
        float* op = out + (size_t)b * Ss * Hh * Dd + (size_t)r * (Hh * Dd) + h * Dd;
        for (int d = 0; d < 64; d++) {
            float s = opart[rl * 64 + d] + opart[(128 + rl) * 64 + d] +
                      opart[(256 + rl) * 64 + d] + opart[(384 + rl) * 64 + d];
            op[d] = s * inv;
        }
    }
    // normalize this row's causal prefix in place
    for (int c = qd; c <= r; c += 4) attnb[(size_t)r * Ss + c] *= inv;
#endif
}

extern "C" void kernel_launch(void* const* d_in, const int* in_sizes, int n_in,
                              void* d_out, int out_size) {
    const float* q = (const float*)d_in[0];
    const float* k = (const float*)d_in[1];
    const float* v = (const float*)d_in[2];
    // d_in[3] = causal mask (deterministic triu) -> handled analytically

    float* out = (float*)d_out;
    float* attn = (float*)d_out + (size_t)Bb * Ss * Hh * Dd;

    cudaFuncSetAttribute(attn_fused_tc, cudaFuncAttributeMaxDynamicSharedMemorySize,
                         SMEM_BYTES);

    dim3 grid(NQT, BHh);
    attn_fused_tc<<<grid, NTHR, SMEM_BYTES>>>(q, k, v, out, attn);
}

// round 9
// speedup vs baseline: 1.2111x; 1.0758x over previous
#include <cuda_runtime.h>
#include <cstdint>

#define Bb 4
#define Ss 2048
#define Hh 16
#define BHh 64
#define Dd 64
#define TM 128
#define TN 128
#define NQT 16
#define NTHR 512
#define SCALE_Q 0.1803368801111204f  /* log2(e)/8 */

// tcgen05 exists only on arch-specific sm_10Xa targets.
#if defined(__CUDA_ARCH__) && (defined(__CUDA_ARCH_FEAT_SM103_ALL) || \
    defined(__CUDA_ARCH_FEAT_SM100_ALL) || defined(__CUDA_ARCH_FEAT_SM101_ALL))
#define USE_TC 1
#else
#define USE_TC 0
#endif

// ---------------- SMEM map (tcgen05 path, all tiles 1024-aligned) ----------------
#define SMEM_TMEMPTR 0
#define SMEM_MBAR_S 64
#define SMEM_MBAR_PV 72
#define SMEM_INV 128            /* 128 floats: per-row 1/L */
#define OFF_QHI 2048
#define OFF_QLO 18432
#define OFF_KHI 34816
#define OFF_KLO 51200
#define OFF_VTH0 67584
#define OFF_VTL0 83968
#define OFF_VTH1 100352
#define OFF_VTL1 116736
#define OFF_PHI 133120
#define OFF_PLO 165888
#define OFF_ONES 198656
#define SMEM_BYTES 202752

// idesc: F32 acc (1<<4), bf16 a (1<<7), bf16 b (1<<10); all K-major
#define IDESC_S ((1u<<4)|(1u<<7)|(1u<<10)|((128/8)<<17)|((128/16)<<24))
#define IDESC_O ((1u<<4)|(1u<<7)|(1u<<10)|((64/8)<<17)|((128/16)<<24))
#define IDESC_L ((1u<<4)|(1u<<7)|(1u<<10)|((16/8)<<17)|((128/16)<<24))

// K-major SW128 descriptor (layout=2, ver=1, SBO=64, LBO=1) — validated
#define DESC_K  ((uint64_t(2)<<61)|(uint64_t(1)<<46)|(uint64_t(64)<<32)|(uint64_t(1)<<16))
#define MAKE_DESC(a) (DESC_K | ((uint64_t)((a) >> 4) & 0x3FFF))

__device__ __forceinline__ uint32_t smem_u32(const void* p) {
    uint32_t a;
    asm("{ .reg .u64 t; cvta.to.shared.u64 t, %1; cvt.u32.u64 %0, t; }" : "=r"(a) : "l"(p));
    return a;
}
__device__ __forceinline__ uint32_t sw128(uint32_t x) { return x ^ ((x >> 3) & 0x70); }

#if USE_TC
__device__ __forceinline__ uint32_t elect_one() {
    uint32_t pred;
    asm volatile("{\n\t.reg .pred p;\n\telect.sync _|p, 0xFFFFFFFF;\n\tselp.b32 %0, 1, 0, p;\n\t}"
                 : "=r"(pred));
    return pred;
}
__device__ __forceinline__ float fexp2(float x) {
    float r;
    asm("ex2.approx.f32 %0, %1;" : "=f"(r) : "f"(x));
    return r;
}
__device__ __forceinline__ uint32_t pack_bf16(float lo, float hi) {
    uint32_t r;
    asm("cvt.rn.bf16x2.f32 %0, %1, %2;" : "=r"(r) : "f"(hi), "f"(lo));
    return r;
}
__device__ __forceinline__ float lofl(uint32_t u) { return __uint_as_float(u << 16); }
__device__ __forceinline__ float hifl(uint32_t u) { return __uint_as_float(u & 0xffff0000u); }

#define MBAR_INIT(addr, cnt) \
    asm volatile("mbarrier.init.shared.b64 [%0], %1;" :: "r"(addr), "r"(cnt) : "memory")
#define MBAR_INVAL(addr) \
    asm volatile("mbarrier.inval.shared.b64 [%0];" :: "r"(addr) : "memory")
#define MBAR_WAIT(addr, parity) do { \
    uint32_t _m = (uint32_t)(addr); uint32_t _p = (uint32_t)(parity); uint32_t _d; \
    asm volatile("{\n\t.reg .pred p;\n\t" \
        "mbarrier.try_wait.parity.acquire.cta.shared::cta.b64 p, [%1], %2;\n\t" \
        "selp.b32 %0, 1, 0, p;\n\t}" : "=r"(_d) : "r"(_m), "r"(_p) : "memory"); \
    if (!_d) { \
        asm volatile("{\n\t.reg .pred P1;\n\t" \
            "WL_%=:\n\t" \
            "mbarrier.try_wait.parity.acquire.cta.shared::cta.b64 P1, [%0], %1, 0x989680;\n\t" \
            "@P1 bra.uni WD_%=;\n\t" \
            "bra.uni WL_%=;\n\t" \
            "WD_%=:\n\t}" :: "r"(_m), "r"(_p) : "memory"); \
    } \
} while (0)

#define TC_ALLOC(smem_addr, ncols) \
    asm volatile("tcgen05.alloc.cta_group::1.sync.aligned.shared::cta.b32 [%0], %1;" \
                 :: "r"((uint32_t)(smem_addr)), "r"((uint32_t)(ncols)) : "memory")
#define TC_DEALLOC(tmem, ncols) \
    asm volatile("tcgen05.dealloc.cta_group::1.sync.aligned.b32 %0, %1;" \
                 :: "r"(tmem), "r"((uint32_t)(ncols)))
#define TC_RELINQ() \
    asm volatile("tcgen05.relinquish_alloc_permit.cta_group::1.sync.aligned;")
#define TC_COMMIT(mbar) \
    asm volatile("tcgen05.commit.cta_group::1.mbarrier::arrive::one.shared::cluster.b64 [%0];" \
                 :: "r"((uint32_t)(mbar)) : "memory")
#define TC_FENCE_BEFORE() asm volatile("tcgen05.fence::before_thread_sync;" ::: "memory")
#define TC_FENCE_AFTER()  asm volatile("tcgen05.fence::after_thread_sync;" ::: "memory")
#define TC_WAIT_LD() asm volatile("tcgen05.wait::ld.sync.aligned;" ::: "memory")
#define FENCE_ASYNC_SHARED() asm volatile("fence.proxy.async.shared::cta;" ::: "memory")

#define TC_LD_X32(r, addr) \
    asm volatile("tcgen05.ld.sync.aligned.32x32b.x32.b32 " \
        "{%0, %1, %2, %3, %4, %5, %6, %7, " \
        " %8, %9, %10, %11, %12, %13, %14, %15, " \
        " %16, %17, %18, %19, %20, %21, %22, %23, " \
        " %24, %25, %26, %27, %28, %29, %30, %31}, [%32];" \
        : "=r"((r)[0]),  "=r"((r)[1]),  "=r"((r)[2]),  "=r"((r)[3]), \
          "=r"((r)[4]),  "=r"((r)[5]),  "=r"((r)[6]),  "=r"((r)[7]), \
          "=r"((r)[8]),  "=r"((r)[9]),  "=r"((r)[10]), "=r"((r)[11]), \
          "=r"((r)[12]), "=r"((r)[13]), "=r"((r)[14]), "=r"((r)[15]), \
          "=r"((r)[16]), "=r"((r)[17]), "=r"((r)[18]), "=r"((r)[19]), \
          "=r"((r)[20]), "=r"((r)[21]), "=r"((r)[22]), "=r"((r)[23]), \
          "=r"((r)[24]), "=r"((r)[25]), "=r"((r)[26]), "=r"((r)[27]), \
          "=r"((r)[28]), "=r"((r)[29]), "=r"((r)[30]), "=r"((r)[31]) \
        : "r"(addr))
#define TC_LD_X1(r0, addr) \
    asm volatile("tcgen05.ld.sync.aligned.32x32b.x1.b32 {%0}, [%1];" : "=r"(r0) : "r"(addr))

__device__ __forceinline__ void mma_bf16(uint32_t d, uint64_t a, uint64_t b,
                                         uint32_t idesc, uint32_t acc) {
    asm volatile("{\n\t.reg .pred p;\n\tsetp.ne.u32 p, %5, 0;\n\t"
                 "tcgen05.mma.cta_group::1.kind::f16 [%0], %1, %2, %3, {%4, %4, %4, %4}, p;\n\t}"
                 :: "r"(d), "l"(a), "l"(b), "r"(idesc), "r"(0u), "r"(acc) : "memory");
}

__device__ __forceinline__ void split8(const float* x, uint4& H, uint4& L) {
    H.x = pack_bf16(x[0], x[1]); H.y = pack_bf16(x[2], x[3]);
    H.z = pack_bf16(x[4], x[5]); H.w = pack_bf16(x[6], x[7]);
    L.x = pack_bf16(x[0] - lofl(H.x), x[1] - hifl(H.x));
    L.y = pack_bf16(x[2] - lofl(H.y), x[3] - hifl(H.y));
    L.z = pack_bf16(x[4] - lofl(H.z), x[5] - hifl(H.z));
    L.w = pack_bf16(x[6] - lofl(H.w), x[7] - hifl(H.w));
}

// 512 threads: thread handles row t>>2, 16 cols starting (t&3)*16
__device__ __forceinline__ void ldg_tile(const float* __restrict__ src, float4* f, int t) {
    const float* p = src + (size_t)(t >> 2) * (Hh * Dd) + (t & 3) * 16;
#pragma unroll
    for (int j = 0; j < 4; j++) f[j] = *(const float4*)(p + 4 * j);
}

// bf16-split + store swizzled K-major (128 rows x 64 bf16)
__device__ __forceinline__ void sts_tile(const float4* f, uint32_t sbp,
                                         uint32_t off_hi, uint32_t off_lo,
                                         float scale, int t) {
    const int r = t >> 2, c0 = (t & 3) * 16;
    const uint32_t rowbase = ((uint32_t)(r >> 3) << 10) + ((uint32_t)(r & 7) << 7);
#pragma unroll
    for (int c = 0; c < 2; c++) {
        float x[8];
        const float4 a = f[2 * c], b = f[2 * c + 1];
        x[0] = a.x * scale; x[1] = a.y * scale; x[2] = a.z * scale; x[3] = a.w * scale;
        x[4] = b.x * scale; x[5] = b.y * scale; x[6] = b.z * scale; x[7] = b.w * scale;
        uint4 H, L;
        split8(x, H, L);
        uint32_t ad = sw128(rowbase + (uint32_t)(c0 + 8 * c) * 2);
        asm volatile("st.shared.v4.b32 [%0], {%1,%2,%3,%4};"
                     :: "r"(sbp + off_hi + ad), "r"(H.x), "r"(H.y), "r"(H.z), "r"(H.w));
        asm volatile("st.shared.v4.b32 [%0], {%1,%2,%3,%4};"
                     :: "r"(sbp + off_lo + ad), "r"(L.x), "r"(L.y), "r"(L.z), "r"(L.w));
    }
}

// bf16-split V + store TRANSPOSED V^T [64 d rows x 128 token cols] K-major
__device__ __forceinline__ void sts_vt(const float4* f, uint32_t sbp,
                                       uint32_t off_hi, uint32_t off_lo, int t) {
    const int tok = t >> 2, c0 = (t & 3) * 16;
    const uint32_t tokpart = ((uint32_t)(tok >> 6) << 13) + ((uint32_t)(tok & 63) << 1);
    const float* x = (const float*)f;
#pragma unroll
    for (int j = 0; j < 16; j++) {
        const int d = c0 + j;
        float val = x[j];
        uint16_t hb;
        asm("cvt.rn.bf16.f32 %0, %1;" : "=h"(hb) : "f"(val));
        float hf = __uint_as_float((uint32_t)hb << 16);
        uint16_t lb;
        asm("cvt.rn.bf16.f32 %0, %1;" : "=h"(lb) : "f"(val - hf));
        uint32_t ad = sw128(((uint32_t)(d >> 3) << 10) + ((uint32_t)(d & 7) << 7) + tokpart);
        asm volatile("st.shared.b16 [%0], %1;" :: "r"(sbp + off_hi + ad), "h"(hb));
        asm volatile("st.shared.b16 [%0], %1;" :: "r"(sbp + off_lo + ad), "h"(lb));
    }
}
#endif  // USE_TC

__global__ __launch_bounds__(NTHR, 1) __cluster_dims__(1, 1, 1)
void attn_fused_tc(const float* __restrict__ q, const float* __restrict__ k,
                   const float* __restrict__ v, float* __restrict__ out,
                   float* __restrict__ attn) {
    extern __shared__ char sm[];
    const int t = threadIdx.x;
    const int w = t >> 5, lid = t & 31;
    const int bh = blockIdx.y, b = bh >> 4, h = bh & 15;
    const int qt = (NQT - 1) - blockIdx.x;  // big tiles first
    const int qr0 = qt * TM;

    const float* qb = q + (size_t)b * Ss * Hh * Dd + (size_t)h * Dd;
    const float* kb = k + (size_t)b * Ss * Hh * Dd + (size_t)h * Dd;
    const float* vb = v + (size_t)b * Ss * Hh * Dd + (size_t)h * Dd;
    float* attnb = attn + (size_t)bh * Ss * Ss;

#if USE_TC
    // ====== two-phase tcgen05: P1 computes O + L (no attn IO); P2 recomputes S
    // ====== and writes NORMALIZED attn once. Saves the 1.1 GB norm read+write.
    const uint32_t sb = smem_u32(sm);

    if (w == 0) TC_ALLOC(sb + SMEM_TMEMPTR, 512);
    if (t == 0) {
        MBAR_INIT(sb + SMEM_MBAR_S, 1);
        MBAR_INIT(sb + SMEM_MBAR_PV, 1);
    }
    for (int i = t; i < 1024; i += NTHR)
        ((uint32_t*)(sm + OFF_ONES))[i] = 0x3F803F80u;
    {
        float4 f[4];
        ldg_tile(qb + (size_t)qr0 * (Hh * Dd), f, t);
        sts_tile(f, sb, OFF_QHI, OFF_QLO, SCALE_Q, t);
        ldg_tile(kb, f, t);
        sts_tile(f, sb, OFF_KHI, OFF_KLO, 1.0f, t);
        ldg_tile(vb, f, t);
        sts_vt(f, sb, OFF_VTH0, OFF_VTL0, t);
    }
    FENCE_ASYNC_SHARED();
    __syncthreads();

    uint32_t tmem;
    asm volatile("ld.shared.b32 %0, [%1];" : "=r"(tmem) : "r"(sb + SMEM_TMEMPTR));
    const uint32_t ST_T[2] = {tmem, tmem + 128};  // double-buffered S^T
    const uint32_t O_T = tmem + 256;              // O: 64 cols, lanes = q rows
    const uint32_t L_T = tmem + 320;              // row sums: 16 cols

    const uint64_t dq_hi = MAKE_DESC(sb + OFF_QHI);
    const uint64_t dq_lo = MAKE_DESC(sb + OFF_QLO);
    const uint64_t dk_hi = MAKE_DESC(sb + OFF_KHI);
    const uint64_t dk_lo = MAKE_DESC(sb + OFF_KLO);
    const uint64_t dvh[2] = {MAKE_DESC(sb + OFF_VTH0), MAKE_DESC(sb + OFF_VTH1)};
    const uint64_t dvl[2] = {MAKE_DESC(sb + OFF_VTL0), MAKE_DESC(sb + OFF_VTL1)};
    const uint64_t dp_hi = MAKE_DESC(sb + OFF_PHI);
    const uint64_t dp_lo = MAKE_DESC(sb + OFF_PLO);
    const uint64_t dones = MAKE_DESC(sb + OFF_ONES);

    // S^T(0) into ST[0]
    if (w == 0 && elect_one()) {
#pragma unroll
        for (int kc = 0; kc < 4; kc++) {
            uint64_t o = (uint64_t)(kc << 1);
            mma_bf16(ST_T[0], dk_hi + o, dq_hi + o, IDESC_S, kc > 0);
            mma_bf16(ST_T[0], dk_hi + o, dq_lo + o, IDESC_S, 1);
            mma_bf16(ST_T[0], dk_lo + o, dq_hi + o, IDESC_S, 1);
        }
        TC_COMMIT(sb + SMEM_MBAR_S);
    }

    float4 fk[4], fv[4];
    if (qt >= 1) {
        ldg_tile(kb + (size_t)TN * (Hh * Dd), fk, t);
        ldg_tile(vb + (size_t)TN * (Hh * Dd), fv, t);
    }

    const int sp = w & 3;
    const int ch = (w >> 2) * 32;          // 32 q-columns per warp (16 warps)
    const int mk = sp * 32 + lid;          // TMEM lane (k token)
    const uint32_t colpart = ((uint32_t)(mk >> 6) << 14) + ((uint32_t)(mk & 63) << 1);
    int s_ph = 0, pv_ph = 0;

    // ================================ PHASE 1 ================================
    for (int kt = 0; kt <= qt; kt++) {
        const int kc0 = kt * TN;
        const int cur = kt & 1, nxt = cur ^ 1;
        const bool diag = (kt == qt);

        MBAR_WAIT(sb + SMEM_MBAR_S, s_ph);
        s_ph ^= 1;
        TC_FENCE_AFTER();

        if (kt < qt) {
            sts_tile(fk, sb, OFF_KHI, OFF_KLO, 1.0f, t);
            FENCE_ASYNC_SHARED();
            __syncthreads();
            if (w == 0 && elect_one()) {
#pragma unroll
                for (int kc = 0; kc < 4; kc++) {
                    uint64_t o = (uint64_t)(kc << 1);
                    mma_bf16(ST_T[nxt], dk_hi + o, dq_hi + o, IDESC_S, kc > 0);
                    mma_bf16(ST_T[nxt], dk_hi + o, dq_lo + o, IDESC_S, 1);
                    mma_bf16(ST_T[nxt], dk_lo + o, dq_hi + o, IDESC_S, 1);
                }
                TC_COMMIT(sb + SMEM_MBAR_S);
            }
        }
        if (kt + 2 <= qt) ldg_tile(kb + (size_t)(kc0 + 2 * TN) * (Hh * Dd), fk, t);

        // exp + mask (no attn write in phase 1)
        uint32_t r[32];
        TC_LD_X32(r, ST_T[cur] + ch);
        TC_WAIT_LD();
#pragma unroll
        for (int j = 0; j < 32; j++) {
            const int ql = ch + j;
            float ev = fexp2(__uint_as_float(r[j]));
            if (diag && (mk > ql)) ev = 0.f;
            r[j] = __float_as_uint(ev);
        }
        // PV(kt-1) must finish before P smem is overwritten
        if (kt > 0) { MBAR_WAIT(sb + SMEM_MBAR_PV, pv_ph); pv_ph ^= 1; }
        // stage P hi/lo (bf16 split)
#pragma unroll
        for (int j = 0; j < 32; j++) {
            const int ql = ch + j;
            float ev = __uint_as_float(r[j]);
            uint16_t hb;
            asm("cvt.rn.bf16.f32 %0, %1;" : "=h"(hb) : "f"(ev));
            float hf = __uint_as_float((uint32_t)hb << 16);
            uint16_t lb;
            asm("cvt.rn.bf16.f32 %0, %1;" : "=h"(lb) : "f"(ev - hf));
            uint32_t ad = sw128(((uint32_t)(ql >> 3) << 10) +
                                ((uint32_t)(ql & 7) << 7) + colpart);
            asm volatile("st.shared.b16 [%0], %1;" :: "r"(sb + OFF_PHI + ad), "h"(hb));
            asm volatile("st.shared.b16 [%0], %1;" :: "r"(sb + OFF_PLO + ad), "h"(lb));
        }
        if (kt < qt) {
            const uint32_t vh = nxt ? OFF_VTH1 : OFF_VTH0;
            const uint32_t vl = nxt ? OFF_VTL1 : OFF_VTL0;
            sts_vt(fv, sb, vh, vl, t);
            if (kt + 2 <= qt) ldg_tile(vb + (size_t)(kc0 + 2 * TN) * (Hh * Dd), fv, t);
        }
        TC_FENCE_BEFORE();
        FENCE_ASYNC_SHARED();
        __syncthreads();

        // O += P·V^T (3-term), L += P·1 (hi AND lo — precision-critical), commit
        if (w == 0 && elect_one()) {
#pragma unroll
            for (int kc = 0; kc < 8; kc++) {
                uint64_t oa = (uint64_t)(((kc >> 2) << 10) + ((kc & 3) << 1));
                uint64_t ob = (uint64_t)(((kc >> 2) << 9) + ((kc & 3) << 1));
                mma_bf16(O_T, dp_hi + oa, dvh[cur] + ob, IDESC_O, !(kt == 0 && kc == 0));
                mma_bf16(O_T, dp_hi + oa, dvl[cur] + ob, IDESC_O, 1);
                mma_bf16(O_T, dp_lo + oa, dvh[cur] + ob, IDESC_O, 1);
            }
#pragma unroll
            for (int kc = 0; kc < 8; kc++) {
                uint64_t oa = (uint64_t)(((kc >> 2) << 10) + ((kc & 3) << 1));
                uint64_t oo = (uint64_t)(((kc >> 2) << 7) + ((kc & 3) << 1));
                mma_bf16(L_T, dp_hi + oa, dones + oo, IDESC_L, !(kt == 0 && kc == 0));
                mma_bf16(L_T, dp_lo + oa, dones + oo, IDESC_L, 1);
            }
            TC_COMMIT(sb + SMEM_MBAR_PV);
        }
    }

    // wait last PV, read L and O (lanes = q rows), store normalized O, stash inv
    MBAR_WAIT(sb + SMEM_MBAR_PV, pv_ph);
    TC_FENCE_AFTER();
    if (w < 8) {
        const int m = (w & 3) * 32 + lid;   // q row
        uint32_t lr;
        TC_LD_X1(lr, L_T);
        uint32_t r[32];
        TC_LD_X32(r, O_T + (w >> 2) * 32);
        TC_WAIT_LD();
        const float inv = 1.0f / __uint_as_float(lr);
        if (w < 4) ((float*)(sm + SMEM_INV))[m] = inv;
        float* op = out + (size_t)b * Ss * Hh * Dd + (size_t)(qr0 + m) * (Hh * Dd) +
                    h * Dd + (w >> 2) * 32;
#pragma unroll
        for (int j = 0; j < 32; j += 4) {
            float4 o4 = make_float4(__uint_as_float(r[j]) * inv,
                                    __uint_as_float(r[j + 1]) * inv,
                                    __uint_as_float(r[j + 2]) * inv,
                                    __uint_as_float(r[j + 3]) * inv);
            *(float4*)(op + j) = o4;
        }
        TC_FENCE_BEFORE();
    }
    __syncthreads();   // inv visible CTA-wide; S engine idle

    // ================================ PHASE 2 ================================
    // Re-run S and write NORMALIZED attn straight from registers.
    {
        float4 f0[4];
        ldg_tile(kb, f0, t);
        sts_tile(f0, sb, OFF_KHI, OFF_KLO, 1.0f, t);
    }
    FENCE_ASYNC_SHARED();
    __syncthreads();
    if (w == 0 && elect_one()) {
#pragma unroll
        for (int kc = 0; kc < 4; kc++) {
            uint64_t o = (uint64_t)(kc << 1);
            mma_bf16(ST_T[0], dk_hi + o, dq_hi + o, IDESC_S, kc > 0);
            mma_bf16(ST_T[0], dk_hi + o, dq_lo + o, IDESC_S, 1);
            mma_bf16(ST_T[0], dk_lo + o, dq_hi + o, IDESC_S, 1);
        }
        TC_COMMIT(sb + SMEM_MBAR_S);
    }
    if (qt >= 1) ldg_tile(kb + (size_t)TN * (Hh * Dd), fk, t);

    // zero-fill masked (strictly upper) region — overlaps S'(0)
    {
        const int zc0 = (qt + 1) * TN;
        const float4 z = make_float4(0.f, 0.f, 0.f, 0.f);
        for (int rr = w; rr < TM; rr += 16) {
            float* rowp = attnb + (size_t)(qr0 + rr) * Ss;
            for (int c = zc0 + lid * 4; c < Ss; c += 128)
                *(float4*)(rowp + c) = z;
        }
    }

    for (int kt = 0; kt <= qt; kt++) {
        const int kc0 = kt * TN;
        const int cur = kt & 1, nxt = cur ^ 1;
        const bool diag = (kt == qt);

        MBAR_WAIT(sb + SMEM_MBAR_S, s_ph);
        s_ph ^= 1;
        TC_FENCE_AFTER();

        if (kt < qt) {
            sts_tile(fk, sb, OFF_KHI, OFF_KLO, 1.0f, t);
            FENCE_ASYNC_SHARED();
            __syncthreads();
            if (w == 0 && elect_one()) {
#pragma unroll
                for (int kc = 0; kc < 4; kc++) {
                    uint64_t o = (uint64_t)(kc << 1);
                    mma_bf16(ST_T[nxt], dk_hi + o, dq_hi + o, IDESC_S, kc > 0);
                    mma_bf16(ST_T[nxt], dk_hi + o, dq_lo + o, IDESC_S, 1);
                    mma_bf16(ST_T[nxt], dk_lo + o, dq_hi + o, IDESC_S, 1);
                }
                TC_COMMIT(sb + SMEM_MBAR_S);
            }
        }
        if (kt + 2 <= qt) ldg_tile(kb + (size_t)(kc0 + 2 * TN) * (Hh * Dd), fk, t);

        // epilogue: exp × inv, mask, single coalesced STG of FINAL attn
        uint32_t r[32];
        TC_LD_X32(r, ST_T[cur] + ch);
        TC_WAIT_LD();
        float* arow = attnb + (size_t)(qr0 + ch) * Ss + kc0 + mk;
#pragma unroll
        for (int j = 0; j < 32; j++) {
            const int ql = ch + j;
            const float iv = ((const float*)(sm + SMEM_INV))[ql];  // broadcast LDS
            float ev = fexp2(__uint_as_float(r[j])) * iv;
            if (diag && (mk > ql)) ev = 0.f;
            arow[(size_t)j * Ss] = ev;
        }
    }

    __syncthreads();
    if (t == 0) { MBAR_INVAL(sb + SMEM_MBAR_S); MBAR_INVAL(sb + SMEM_MBAR_PV); }
    __syncthreads();
    if (w == 0) {
        TC_RELINQ();
        TC_DEALLOC(tmem, 512);
    }
#else
    // ============== correct (slow) fallback for the plain-sm_103 pass ==============
    float* opart = (float*)sm;              // [4][128][64]
    float* lpart = (float*)(sm + 131072);   // [4][128]
    const int rl = t >> 2;                  // local row 0..127
    const int r = qr0 + rl;
    const int qd = t & 3;
    const float* qrow = qb + (size_t)r * (Hh * Dd);
    float qreg[64];
#pragma unroll
    for (int d = 0; d < 64; d++) qreg[d] = qrow[d] * 0.125f;
    float o[64];
#pragma unroll
    for (int d = 0; d < 64; d++) o[d] = 0.f;
    float ls = 0.f;
    for (int kk = qd; kk <= r; kk += 4) {
        const float* krow = kb + (size_t)kk * (Hh * Dd);
        float s = 0.f;
#pragma unroll
        for (int d = 0; d < 64; d++) s += qreg[d] * krow[d];
        float e = __expf(s);
        attnb[(size_t)r * Ss + kk] = e;
        ls += e;
        const float* vrow = vb + (size_t)kk * (Hh * Dd);
#pragma unroll
        for (int d = 0; d < 64; d++) o[d] += e * vrow[d];
    }
#pragma unroll
    for (int d = 0; d < 64; d++) opart[((qd << 7) + rl) * 64 + d] = o[d];
    lpart[(qd << 7) + rl] = ls;
    for (int c = r + 1 + qd; c < Ss; c += 4) attnb[(size_t)r * Ss + c] = 0.f;
    __syncthreads();
    float tot = lpart[rl] + lpart[128 + rl] + lpart[256 + rl] + lpart[384 + rl];
    float inv = 1.0f / tot;
    if (qd == 0) {
        float* op = out + (size_t)b * Ss * Hh * Dd + (size_t)r * (Hh * Dd) + h * Dd;
        for (int d = 0; d < 64; d++) {
            float s = opart[rl * 64 + d] + opart[(128 + rl) * 64 + d] +
                      opart[(256 + rl) * 64 + d] + opart[(384 + rl) * 64 + d];
            op[d] = s * inv;
        }
    }
    for (int c = qd; c <= r; c += 4) attnb[(size_t)r * Ss + c] *= inv;
#endif
}

extern "C" void kernel_launch(void* const* d_in, const int* in_sizes, int n_in,
                              void* d_out, int out_size) {
    const float* q = (const float*)d_in[0];
    const float* k = (const float*)d_in[1];
    const float* v = (const float*)d_in[2];
    // d_in[3] = causal mask (deterministic triu) -> handled analytically

    float* out = (float*)d_out;
    float* attn = (float*)d_out + (size_t)Bb * Ss * Hh * Dd;

    cudaFuncSetAttribute(attn_fused_tc, cudaFuncAttributeMaxDynamicSharedMemorySize,
                         SMEM_BYTES);

    dim3 grid(NQT, BHh);
    attn_fused_tc<<<grid, NTHR, SMEM_BYTES>>>(q, k, v, out, attn);
}